// round 2
// baseline (speedup 1.0000x reference)
#include <cuda_runtime.h>
#include <cstdint>
#include <cstddef>

// Problem shape (fixed by the dataset): B=8192, T=16, C=512, H=8, DH=64
#define BT_TOTAL 131072          // B*T
#define B_TOTAL  8192
#define C_DIM    512

// ---------------------------------------------------------------------------
// Scratch (device globals; no allocations allowed)
// ---------------------------------------------------------------------------
__device__ float g_q[BT_TOTAL * C_DIM];    // 256 MiB
__device__ float g_k[BT_TOTAL * C_DIM];
__device__ float g_v[BT_TOTAL * C_DIM];
__device__ float g_ctx[BT_TOTAL * C_DIM];

// ---------------------------------------------------------------------------
// Helpers
// ---------------------------------------------------------------------------
__device__ __forceinline__ float f2tf32(float x) {
    uint32_t u;
    asm("cvt.rna.tf32.f32 %0, %1;" : "=r"(u) : "f"(x));
    return __uint_as_float(u);
}

__device__ __forceinline__ void mma_tf32(float* d, const uint32_t* a, const uint32_t* b) {
    asm volatile(
        "mma.sync.aligned.m16n8k8.row.col.f32.tf32.tf32.f32 "
        "{%0,%1,%2,%3}, {%4,%5,%6,%7}, {%8,%9}, {%0,%1,%2,%3};\n"
        : "+f"(d[0]), "+f"(d[1]), "+f"(d[2]), "+f"(d[3])
        : "r"(a[0]), "r"(a[1]), "r"(a[2]), "r"(a[3]),
          "r"(b[0]), "r"(b[1]));
}

// ---------------------------------------------------------------------------
// TF32 GEMM:  C[m,n] = sum_k A[m,k] * B[n,k]  (+ bias[n])
// M = gridDim.y*128, N = 512, K = 512.  Block 256 threads, tile 128x128x32.
// ---------------------------------------------------------------------------
__global__ __launch_bounds__(256, 1)
void gemm_tf32_kernel(const float* __restrict__ A, const float* __restrict__ B,
                      float* __restrict__ Cout, const float* __restrict__ bias) {
    constexpr int K = 512;
    constexpr int N = 512;
    constexpr int LDS = 36;                 // padded stride (floats)
    constexpr int BUF = 128 * LDS;          // one tile buffer

    extern __shared__ float smem[];
    float* As = smem;                       // [2][128][36]
    float* Bs = smem + 2 * BUF;             // [2][128][36]

    const int tid   = threadIdx.x;
    const int lane  = tid & 31;
    const int warp  = tid >> 5;
    const int warpM = warp >> 2;            // 0..1  (64-row slab)
    const int warpN = warp & 3;             // 0..3  (32-col slab)
    const int gid   = lane >> 2;            // 0..7
    const int tig   = lane & 3;             // 0..3

    const int bm = blockIdx.y;
    const int bn = blockIdx.x;

    const float* Ag = A + (size_t)bm * 128 * K;
    const float* Bg = B + (size_t)bn * 128 * K;

    const int lrow = tid >> 3;              // 0..31
    const int lcol = (tid & 7) << 2;        // 0,4,...,28

    float4 aR[4], bR[4];
    float acc[4][4][4];
    #pragma unroll
    for (int i = 0; i < 4; ++i)
        #pragma unroll
        for (int j = 0; j < 4; ++j)
            #pragma unroll
            for (int r = 0; r < 4; ++r) acc[i][j][r] = 0.f;

    // ---- global -> regs for k-tile kt ----
    #define G2R(kt)                                                              \
        {                                                                        \
            const float* ap = Ag + (size_t)lrow * K + (kt) * 32 + lcol;          \
            const float* bp = Bg + (size_t)lrow * K + (kt) * 32 + lcol;          \
            _Pragma("unroll")                                                    \
            for (int r = 0; r < 4; ++r) {                                        \
                aR[r] = *(const float4*)(ap + (size_t)r * 32 * K);               \
                bR[r] = *(const float4*)(bp + (size_t)r * 32 * K);               \
            }                                                                    \
        }

    // ---- regs -> smem (tf32-rounded) ----
    #define R2S(buf)                                                             \
        {                                                                        \
            float* as = As + (buf) * BUF;                                        \
            float* bs = Bs + (buf) * BUF;                                        \
            _Pragma("unroll")                                                    \
            for (int r = 0; r < 4; ++r) {                                        \
                int row = lrow + r * 32;                                         \
                float4 av = make_float4(f2tf32(aR[r].x), f2tf32(aR[r].y),        \
                                        f2tf32(aR[r].z), f2tf32(aR[r].w));       \
                float4 bv = make_float4(f2tf32(bR[r].x), f2tf32(bR[r].y),        \
                                        f2tf32(bR[r].z), f2tf32(bR[r].w));       \
                *(float4*)(as + row * LDS + lcol) = av;                          \
                *(float4*)(bs + row * LDS + lcol) = bv;                          \
            }                                                                    \
        }

    G2R(0);
    R2S(0);
    __syncthreads();

    #pragma unroll 1
    for (int kt = 0; kt < 16; ++kt) {
        const int cur = kt & 1;
        if (kt + 1 < 16) G2R(kt + 1);

        const float* as = As + cur * BUF;
        const float* bs = Bs + cur * BUF;
        #pragma unroll
        for (int ks = 0; ks < 4; ++ks) {
            const int kb = ks * 8;
            uint32_t aF[4][4];
            uint32_t bF[4][2];
            #pragma unroll
            for (int mt = 0; mt < 4; ++mt) {
                const int rb = warpM * 64 + mt * 16;
                aF[mt][0] = __float_as_uint(as[(rb + gid)     * LDS + kb + tig]);
                aF[mt][1] = __float_as_uint(as[(rb + gid + 8) * LDS + kb + tig]);
                aF[mt][2] = __float_as_uint(as[(rb + gid)     * LDS + kb + tig + 4]);
                aF[mt][3] = __float_as_uint(as[(rb + gid + 8) * LDS + kb + tig + 4]);
            }
            #pragma unroll
            for (int nt = 0; nt < 4; ++nt) {
                const int cb = warpN * 32 + nt * 8;
                bF[nt][0] = __float_as_uint(bs[(cb + gid) * LDS + kb + tig]);
                bF[nt][1] = __float_as_uint(bs[(cb + gid) * LDS + kb + tig + 4]);
            }
            #pragma unroll
            for (int mt = 0; mt < 4; ++mt)
                #pragma unroll
                for (int nt = 0; nt < 4; ++nt)
                    mma_tf32(acc[mt][nt], aF[mt], bF[nt]);
        }

        if (kt + 1 < 16) R2S((kt + 1) & 1);
        __syncthreads();
    }

    // ---- epilogue ----
    const size_t cbase = (size_t)bm * 128 * N + (size_t)bn * 128;
    #pragma unroll
    for (int mt = 0; mt < 4; ++mt) {
        const int r0 = warpM * 64 + mt * 16 + gid;
        #pragma unroll
        for (int nt = 0; nt < 4; ++nt) {
            const int c0 = warpN * 32 + nt * 8 + tig * 2;
            float b0 = 0.f, b1 = 0.f;
            if (bias) { b0 = bias[bn * 128 + c0]; b1 = bias[bn * 128 + c0 + 1]; }
            size_t o = cbase + (size_t)r0 * N + c0;
            float2 lo = make_float2(acc[mt][nt][0] + b0, acc[mt][nt][1] + b1);
            float2 hi = make_float2(acc[mt][nt][2] + b0, acc[mt][nt][3] + b1);
            *(float2*)(Cout + o)         = lo;
            *(float2*)(Cout + o + 8 * N) = hi;
        }
    }
    #undef G2R
    #undef R2S
}

// ---------------------------------------------------------------------------
// Fused attention middle: one CTA per batch item b.
//   m = LN(mask[b]); sym = (m m^T)/sqrt(C), zero diag
//   sim[h,i,j] = (q_i . k_j)/8 + sym[i,j]*beta[h]; softmax over j
//   ctx[i, h*64+d] = sum_j attn[h,i,j] * v[j, h*64+d]
// ---------------------------------------------------------------------------
__global__ __launch_bounds__(256, 1)
void attn_kernel(const float* __restrict__ mask,
                 const float* __restrict__ ln_g, const float* __restrict__ ln_b,
                 const float* __restrict__ beta) {
    constexpr int PADC = 516;
    extern __shared__ float sm[];
    float* sQ   = sm;                        // 16*516
    float* sK   = sQ + 16 * PADC;            // 16*516
    float* sB   = sK + 16 * PADC;            // 16*516 : m, then v
    float* sSym = sB + 16 * PADC;            // 256
    float* sSim = sSym + 256;                // 2048  [h][i][j]

    const int tid = threadIdx.x;
    const int b   = blockIdx.x;
    const size_t base = (size_t)b * (16 * 512);

    // load mask[b] into sB
    for (int idx = tid; idx < 8192; idx += 256) {
        int r = idx >> 9, c = idx & 511;
        sB[r * PADC + c] = mask[base + idx];
    }
    __syncthreads();

    // layernorm, warp per row (2 passes over 16 rows)
    {
        const int warp = tid >> 5, lane = tid & 31;
        #pragma unroll
        for (int p = 0; p < 2; ++p) {
            float* row = sB + (warp + p * 8) * PADC;
            float s = 0.f, sq = 0.f;
            #pragma unroll 4
            for (int c = lane; c < 512; c += 32) { float x = row[c]; s += x; sq += x * x; }
            #pragma unroll
            for (int o = 16; o; o >>= 1) {
                s  += __shfl_xor_sync(0xffffffffu, s,  o);
                sq += __shfl_xor_sync(0xffffffffu, sq, o);
            }
            const float mu  = s * (1.f / 512.f);
            const float var = sq * (1.f / 512.f) - mu * mu;
            const float inv = rsqrtf(var + 1e-5f);
            #pragma unroll 4
            for (int c = lane; c < 512; c += 32)
                row[c] = (row[c] - mu) * inv * ln_g[c] + ln_b[c];
        }
    }
    __syncthreads();

    // sym: one thread per (i,j)
    {
        const int i = tid >> 4, j = tid & 15;
        const float4* mi = (const float4*)(sB + i * PADC);
        const float4* mj = (const float4*)(sB + j * PADC);
        float s = 0.f;
        #pragma unroll 8
        for (int c = 0; c < 128; ++c) {
            float4 a = mi[c], bb = mj[c];
            s += a.x * bb.x + a.y * bb.y + a.z * bb.z + a.w * bb.w;
        }
        sSym[tid] = (i == j) ? 0.f : s * 0.044194173824159216f;  // 1/sqrt(512)
    }
    __syncthreads();

    // load q,k,v (v overwrites m in sB — safe after the sync above)
    for (int idx = tid; idx < 8192; idx += 256) {
        int r = idx >> 9, c = idx & 511;
        sQ[r * PADC + c] = g_q[base + idx];
        sK[r * PADC + c] = g_k[base + idx];
        sB[r * PADC + c] = g_v[base + idx];
    }
    __syncthreads();

    // sim + bias: 2048 dot products of length 64
    #pragma unroll 1
    for (int it = 0; it < 8; ++it) {
        const int idx = tid + it * 256;
        const int h = idx >> 8;
        const int i = (idx >> 4) & 15;
        const int j = idx & 15;
        const float4* qp = (const float4*)(sQ + i * PADC + h * 64);
        const float4* kp = (const float4*)(sK + j * PADC + h * 64);
        float s = 0.f;
        #pragma unroll
        for (int c = 0; c < 16; ++c) {
            float4 a = qp[c], bb = kp[c];
            s += a.x * bb.x + a.y * bb.y + a.z * bb.z + a.w * bb.w;
        }
        sSim[idx] = s * 0.125f + sSym[i * 16 + j] * beta[h];
    }
    __syncthreads();

    // softmax over j: one thread per (h,i) row
    if (tid < 128) {
        float* row = sSim + tid * 16;
        float mx = row[0];
        #pragma unroll
        for (int j = 1; j < 16; ++j) mx = fmaxf(mx, row[j]);
        float s = 0.f;
        #pragma unroll
        for (int j = 0; j < 16; ++j) { float e = expf(row[j] - mx); row[j] = e; s += e; }
        const float inv = 1.f / s;
        #pragma unroll
        for (int j = 0; j < 16; ++j) row[j] *= inv;
    }
    __syncthreads();

    // ctx = attn @ v : one thread per output element, 32 passes
    #pragma unroll 1
    for (int it = 0; it < 32; ++it) {
        const int idx = tid + it * 256;        // 0..8191
        const int i = idx >> 9;
        const int e = idx & 511;
        const int h = e >> 6;
        const float* arow = sSim + (h * 16 + i) * 16;
        float a = 0.f;
        #pragma unroll
        for (int j = 0; j < 16; ++j) a += arow[j] * sB[j * PADC + e];
        g_ctx[base + idx] = a;
    }
}

// ---------------------------------------------------------------------------
// Launch
// ---------------------------------------------------------------------------
extern "C" void kernel_launch(void* const* d_in, const int* in_sizes, int n_in,
                              void* d_out, int out_size) {
    const float* x    = (const float*)d_in[0];
    const float* mask = (const float*)d_in[1];
    const float* w_q  = (const float*)d_in[2];
    const float* w_k  = (const float*)d_in[3];
    const float* w_v  = (const float*)d_in[4];
    const float* w_o  = (const float*)d_in[5];
    const float* b_o  = (const float*)d_in[6];
    const float* beta = (const float*)d_in[7];
    const float* ln_g = (const float*)d_in[8];
    const float* ln_b = (const float*)d_in[9];
    float* out = (float*)d_out;

    float *q, *k, *v, *ctx;
    cudaGetSymbolAddress((void**)&q,   g_q);
    cudaGetSymbolAddress((void**)&k,   g_k);
    cudaGetSymbolAddress((void**)&v,   g_v);
    cudaGetSymbolAddress((void**)&ctx, g_ctx);

    const int bt = in_sizes[0] / C_DIM;       // B*T = 131072
    const int bb = bt / 16;                   // B   = 8192

    const int gemm_smem = 2 * 2 * 128 * 36 * 4;   // 73728
    const int attn_smem = (3 * 16 * 516 + 256 + 2048) * 4;  // 108288
    cudaFuncSetAttribute(gemm_tf32_kernel, cudaFuncAttributeMaxDynamicSharedMemorySize, gemm_smem);
    cudaFuncSetAttribute(attn_kernel,      cudaFuncAttributeMaxDynamicSharedMemorySize, attn_smem);

    dim3 grid(4, bt / 128);                   // N/128 x M/128
    gemm_tf32_kernel<<<grid, 256, gemm_smem>>>(x,   w_q, q,   nullptr);
    gemm_tf32_kernel<<<grid, 256, gemm_smem>>>(x,   w_k, k,   nullptr);
    gemm_tf32_kernel<<<grid, 256, gemm_smem>>>(x,   w_v, v,   nullptr);
    attn_kernel<<<bb, 256, attn_smem>>>(mask, ln_g, ln_b, beta);
    gemm_tf32_kernel<<<grid, 256, gemm_smem>>>(ctx, w_o, out, b_o);
}

// round 4
// speedup vs baseline: 1.0503x; 1.0503x over previous
#include <cuda_runtime.h>
#include <cstdint>
#include <cstddef>

// Problem shape (fixed by the dataset): B=8192, T=16, C=512, H=8, DH=64
#define BT_TOTAL 131072          // B*T
#define B_TOTAL  8192
#define C_DIM    512

// ---------------------------------------------------------------------------
// Scratch (device globals; no allocations allowed)
// ---------------------------------------------------------------------------
__device__ float g_q[BT_TOTAL * C_DIM];    // 256 MiB
__device__ float g_k[BT_TOTAL * C_DIM];
__device__ float g_v[BT_TOTAL * C_DIM];
__device__ float g_ctx[BT_TOTAL * C_DIM];

// ---------------------------------------------------------------------------
// Helpers
// ---------------------------------------------------------------------------
__device__ __forceinline__ uint32_t smem_u32(const void* p) {
    uint32_t a;
    asm("{ .reg .u64 t; cvta.to.shared.u64 t, %1; cvt.u32.u64 %0, t; }" : "=r"(a) : "l"(p));
    return a;
}
__device__ __forceinline__ float f2tf32(float x) {
    uint32_t u;
    asm("cvt.rna.tf32.f32 %0, %1;" : "=r"(u) : "f"(x));
    return __uint_as_float(u);
}

__device__ __forceinline__ void mma_tf32(float* d, const uint32_t* a, const uint32_t* b) {
    asm volatile(
        "mma.sync.aligned.m16n8k8.row.col.f32.tf32.tf32.f32 "
        "{%0,%1,%2,%3}, {%4,%5,%6,%7}, {%8,%9}, {%0,%1,%2,%3};\n"
        : "+f"(d[0]), "+f"(d[1]), "+f"(d[2]), "+f"(d[3])
        : "r"(a[0]), "r"(a[1]), "r"(a[2]), "r"(a[3]),
          "r"(b[0]), "r"(b[1]));
}

// ---------------------------------------------------------------------------
// TF32 GEMM:  C[m,n] = sum_k A[m,k] * B[n,k]  (+ bias[n])
// M = gridDim.y*128, N = 512, K = 512.  Block 256 threads, tile 128x128x32.
// (Unchanged from the passing R2 kernel — measured at ~96% of the mma.sync
//  tf32 ceiling; do not touch.)
// ---------------------------------------------------------------------------
__global__ __launch_bounds__(256, 1)
void gemm_tf32_kernel(const float* __restrict__ A, const float* __restrict__ B,
                      float* __restrict__ Cout, const float* __restrict__ bias) {
    constexpr int K = 512;
    constexpr int N = 512;
    constexpr int LDS = 36;                 // padded stride (floats)
    constexpr int BUF = 128 * LDS;          // one tile buffer

    extern __shared__ float smem[];
    float* As = smem;                       // [2][128][36]
    float* Bs = smem + 2 * BUF;             // [2][128][36]

    const int tid   = threadIdx.x;
    const int lane  = tid & 31;
    const int warp  = tid >> 5;
    const int warpM = warp >> 2;            // 0..1  (64-row slab)
    const int warpN = warp & 3;             // 0..3  (32-col slab)
    const int gid   = lane >> 2;            // 0..7
    const int tig   = lane & 3;             // 0..3

    const int bm = blockIdx.y;
    const int bn = blockIdx.x;

    const float* Ag = A + (size_t)bm * 128 * K;
    const float* Bg = B + (size_t)bn * 128 * K;

    const int lrow = tid >> 3;              // 0..31
    const int lcol = (tid & 7) << 2;        // 0,4,...,28

    float4 aR[4], bR[4];
    float acc[4][4][4];
    #pragma unroll
    for (int i = 0; i < 4; ++i)
        #pragma unroll
        for (int j = 0; j < 4; ++j)
            #pragma unroll
            for (int r = 0; r < 4; ++r) acc[i][j][r] = 0.f;

    // ---- global -> regs for k-tile kt ----
    #define G2R(kt)                                                              \
        {                                                                        \
            const float* ap = Ag + (size_t)lrow * K + (kt) * 32 + lcol;          \
            const float* bp = Bg + (size_t)lrow * K + (kt) * 32 + lcol;          \
            _Pragma("unroll")                                                    \
            for (int r = 0; r < 4; ++r) {                                        \
                aR[r] = *(const float4*)(ap + (size_t)r * 32 * K);               \
                bR[r] = *(const float4*)(bp + (size_t)r * 32 * K);               \
            }                                                                    \
        }

    // ---- regs -> smem (tf32-rounded) ----
    #define R2S(buf)                                                             \
        {                                                                        \
            float* as = As + (buf) * BUF;                                        \
            float* bs = Bs + (buf) * BUF;                                        \
            _Pragma("unroll")                                                    \
            for (int r = 0; r < 4; ++r) {                                        \
                int row = lrow + r * 32;                                         \
                float4 av = make_float4(f2tf32(aR[r].x), f2tf32(aR[r].y),        \
                                        f2tf32(aR[r].z), f2tf32(aR[r].w));       \
                float4 bv = make_float4(f2tf32(bR[r].x), f2tf32(bR[r].y),        \
                                        f2tf32(bR[r].z), f2tf32(bR[r].w));       \
                *(float4*)(as + row * LDS + lcol) = av;                          \
                *(float4*)(bs + row * LDS + lcol) = bv;                          \
            }                                                                    \
        }

    G2R(0);
    R2S(0);
    __syncthreads();

    #pragma unroll 1
    for (int kt = 0; kt < 16; ++kt) {
        const int cur = kt & 1;
        if (kt + 1 < 16) G2R(kt + 1);

        const float* as = As + cur * BUF;
        const float* bs = Bs + cur * BUF;
        #pragma unroll
        for (int ks = 0; ks < 4; ++ks) {
            const int kb = ks * 8;
            uint32_t aF[4][4];
            uint32_t bF[4][2];
            #pragma unroll
            for (int mt = 0; mt < 4; ++mt) {
                const int rb = warpM * 64 + mt * 16;
                aF[mt][0] = __float_as_uint(as[(rb + gid)     * LDS + kb + tig]);
                aF[mt][1] = __float_as_uint(as[(rb + gid + 8) * LDS + kb + tig]);
                aF[mt][2] = __float_as_uint(as[(rb + gid)     * LDS + kb + tig + 4]);
                aF[mt][3] = __float_as_uint(as[(rb + gid + 8) * LDS + kb + tig + 4]);
            }
            #pragma unroll
            for (int nt = 0; nt < 4; ++nt) {
                const int cb = warpN * 32 + nt * 8;
                bF[nt][0] = __float_as_uint(bs[(cb + gid) * LDS + kb + tig]);
                bF[nt][1] = __float_as_uint(bs[(cb + gid) * LDS + kb + tig + 4]);
            }
            #pragma unroll
            for (int mt = 0; mt < 4; ++mt)
                #pragma unroll
                for (int nt = 0; nt < 4; ++nt)
                    mma_tf32(acc[mt][nt], aF[mt], bF[nt]);
        }

        if (kt + 1 < 16) R2S((kt + 1) & 1);
        __syncthreads();
    }

    // ---- epilogue ----
    const size_t cbase = (size_t)bm * 128 * N + (size_t)bn * 128;
    #pragma unroll
    for (int mt = 0; mt < 4; ++mt) {
        const int r0 = warpM * 64 + mt * 16 + gid;
        #pragma unroll
        for (int nt = 0; nt < 4; ++nt) {
            const int c0 = warpN * 32 + nt * 8 + tig * 2;
            float b0 = 0.f, b1 = 0.f;
            if (bias) { b0 = bias[bn * 128 + c0]; b1 = bias[bn * 128 + c0 + 1]; }
            size_t o = cbase + (size_t)r0 * N + c0;
            float2 lo = make_float2(acc[mt][nt][0] + b0, acc[mt][nt][1] + b1);
            float2 hi = make_float2(acc[mt][nt][2] + b0, acc[mt][nt][3] + b1);
            *(float2*)(Cout + o)         = lo;
            *(float2*)(Cout + o + 8 * N) = hi;
        }
    }
    #undef G2R
    #undef R2S
}

// ---------------------------------------------------------------------------
// Fused attention middle: CTA per batch. m/k in smem; q,v via L1 global.
//   m = LN(mask[b]); sym = (m m^T)/sqrt(C), zero diag
//   sim[h,i,j] = (q_i . k_j)/8 + sym[i,j]*beta[h]; softmax over j
//   ctx[i, h*64+d] = sum_j attn[h,i,j] * v[j, h*64+d]
// ---------------------------------------------------------------------------
__global__ __launch_bounds__(256)
void attn_kernel(const float* __restrict__ mask,
                 const float* __restrict__ ln_g, const float* __restrict__ ln_b,
                 const float* __restrict__ beta) {
    constexpr int PADC = 516;
    extern __shared__ float sm[];
    float* sM   = sm;                   // 16*516
    float* sK   = sM + 16 * PADC;       // 16*516
    float* sSym = sK + 16 * PADC;       // 256
    float* sSim = sSym + 256;           // 2048

    const int tid  = threadIdx.x;
    const int warp = tid >> 5;
    const int lane = tid & 31;
    const size_t base = (size_t)blockIdx.x * 8192;

    // --- async prefetch k -> sK (overlaps LN + sym) ---
    {
        const uint32_t skb = smem_u32(sK);
        const float* kg = g_k + base;
        #pragma unroll
        for (int r = 0; r < 8; ++r) {
            int f = tid + 256 * r;               // float4 index 0..2047
            int row = f >> 7, c4 = f & 127;
            uint32_t dst = skb + (uint32_t)(row * PADC + c4 * 4) * 4u;
            const float* src = kg + (size_t)row * 512 + c4 * 4;
            asm volatile("cp.async.ca.shared.global [%0], [%1], 16;" :: "r"(dst), "l"(src));
        }
        asm volatile("cp.async.commit_group;" ::: "memory");
    }

    // --- layernorm(mask) -> sM : warp per row, 2 rows/warp ---
    #pragma unroll
    for (int p = 0; p < 2; ++p) {
        const int r = warp + p * 8;
        const float4* mg = (const float4*)(mask + base + (size_t)r * 512);
        float4 vv[4];
        float s = 0.f, sq = 0.f;
        #pragma unroll
        for (int u = 0; u < 4; ++u) {
            vv[u] = mg[lane + 32 * u];
            s  += vv[u].x + vv[u].y + vv[u].z + vv[u].w;
            sq += vv[u].x * vv[u].x + vv[u].y * vv[u].y + vv[u].z * vv[u].z + vv[u].w * vv[u].w;
        }
        #pragma unroll
        for (int o = 16; o; o >>= 1) {
            s  += __shfl_xor_sync(0xffffffffu, s,  o);
            sq += __shfl_xor_sync(0xffffffffu, sq, o);
        }
        const float mu  = s * (1.f / 512.f);
        const float inv = rsqrtf(sq * (1.f / 512.f) - mu * mu + 1e-5f);
        float4* mr = (float4*)(sM + r * PADC);
        const float4* gg = (const float4*)ln_g;
        const float4* bv = (const float4*)ln_b;
        #pragma unroll
        for (int u = 0; u < 4; ++u) {
            float4 g4 = gg[lane + 32 * u], b4 = bv[lane + 32 * u];
            mr[lane + 32 * u] = make_float4((vv[u].x - mu) * inv * g4.x + b4.x,
                                            (vv[u].y - mu) * inv * g4.y + b4.y,
                                            (vv[u].z - mu) * inv * g4.z + b4.z,
                                            (vv[u].w - mu) * inv * g4.w + b4.w);
        }
    }
    __syncthreads();

    // --- sym = (m m^T)/sqrt(C), zero diagonal: one thread per (i,j) ---
    {
        const int i = tid >> 4, j = tid & 15;
        const float4* mi = (const float4*)(sM + i * PADC);
        const float4* mj = (const float4*)(sM + j * PADC);
        float s = 0.f;
        #pragma unroll 8
        for (int c = 0; c < 128; ++c) {
            float4 a = mi[c], b = mj[c];
            s += a.x * b.x + a.y * b.y + a.z * b.z + a.w * b.w;
        }
        sSym[tid] = (i == j) ? 0.f : s * 0.044194173824159216f;  // 1/sqrt(512)
    }
    asm volatile("cp.async.wait_group 0;" ::: "memory");
    __syncthreads();

    // --- sim[h,i,j] = q_i.k_j/8 + sym*beta[h] (q broadcast via L1) ---
    {
        const float* qg = g_q + base;
        #pragma unroll 1
        for (int it = 0; it < 8; ++it) {
            const int idx = tid + it * 256;
            const int h = idx >> 8, i = (idx >> 4) & 15, j = idx & 15;
            const float4* qp = (const float4*)(qg + (size_t)i * 512 + h * 64);
            const float4* kp = (const float4*)(sK + j * PADC + h * 64);
            float s = 0.f;
            #pragma unroll
            for (int c = 0; c < 16; ++c) {
                float4 a = qp[c], b = kp[c];
                s += a.x * b.x + a.y * b.y + a.z * b.z + a.w * b.w;
            }
            sSim[idx] = s * 0.125f + sSym[i * 16 + j] * beta[h];
        }
    }
    __syncthreads();

    // --- softmax over j: one thread per (h,i) row ---
    if (tid < 128) {
        float* row = sSim + tid * 16;
        float mx = row[0];
        #pragma unroll
        for (int j = 1; j < 16; ++j) mx = fmaxf(mx, row[j]);
        float s = 0.f;
        #pragma unroll
        for (int j = 0; j < 16; ++j) { float e = __expf(row[j] - mx); row[j] = e; s += e; }
        const float inv = 1.f / s;
        #pragma unroll
        for (int j = 0; j < 16; ++j) row[j] *= inv;
    }
    __syncthreads();

    // --- ctx = attn @ v (v via coalesced L1 global loads) ---
    {
        const float* vg = g_v + base;
        #pragma unroll 1
        for (int it = 0; it < 32; ++it) {
            const int idx = tid + it * 256;
            const int i = idx >> 9, e = idx & 511, h = e >> 6;
            const float* ar = sSim + (h * 16 + i) * 16;
            float a = 0.f;
            #pragma unroll
            for (int j = 0; j < 16; ++j) a += ar[j] * vg[(size_t)j * 512 + e];
            g_ctx[base + idx] = a;
        }
    }
}

// ---------------------------------------------------------------------------
// Launch
// ---------------------------------------------------------------------------
extern "C" void kernel_launch(void* const* d_in, const int* in_sizes, int n_in,
                              void* d_out, int out_size) {
    const float* x    = (const float*)d_in[0];
    const float* mask = (const float*)d_in[1];
    const float* w_q  = (const float*)d_in[2];
    const float* w_k  = (const float*)d_in[3];
    const float* w_v  = (const float*)d_in[4];
    const float* w_o  = (const float*)d_in[5];
    const float* b_o  = (const float*)d_in[6];
    const float* beta = (const float*)d_in[7];
    const float* ln_g = (const float*)d_in[8];
    const float* ln_b = (const float*)d_in[9];
    float* out = (float*)d_out;

    float *q, *k, *v, *ctx;
    cudaGetSymbolAddress((void**)&q,   g_q);
    cudaGetSymbolAddress((void**)&k,   g_k);
    cudaGetSymbolAddress((void**)&v,   g_v);
    cudaGetSymbolAddress((void**)&ctx, g_ctx);

    const int bt = in_sizes[0] / C_DIM;       // B*T = 131072
    const int bb = bt / 16;                   // B   = 8192

    const int gemm_smem = 2 * 2 * 128 * 36 * 4;              // 73728
    const int attn_smem = (2 * 16 * 516 + 256 + 2048) * 4;   // 75264
    cudaFuncSetAttribute(gemm_tf32_kernel, cudaFuncAttributeMaxDynamicSharedMemorySize, gemm_smem);
    cudaFuncSetAttribute(attn_kernel,      cudaFuncAttributeMaxDynamicSharedMemorySize, attn_smem);

    dim3 grid(4, bt / 128);                   // N/128 x M/128
    gemm_tf32_kernel<<<grid, 256, gemm_smem>>>(x,   w_q, q,   nullptr);
    gemm_tf32_kernel<<<grid, 256, gemm_smem>>>(x,   w_k, k,   nullptr);
    gemm_tf32_kernel<<<grid, 256, gemm_smem>>>(x,   w_v, v,   nullptr);
    attn_kernel<<<bb, 256, attn_smem>>>(mask, ln_g, ln_b, beta);
    gemm_tf32_kernel<<<grid, 256, gemm_smem>>>(ctx, w_o, out, b_o);
}

// round 5
// speedup vs baseline: 1.1374x; 1.0829x over previous
#include <cuda_runtime.h>
#include <cstdint>
#include <cstddef>

// Problem shape (fixed by the dataset): B=8192, T=16, C=512, H=8, DH=64
#define BT_TOTAL 131072          // B*T
#define B_TOTAL  8192
#define C_DIM    512

// ---------------------------------------------------------------------------
// Scratch (device globals; no allocations allowed)
// ---------------------------------------------------------------------------
__device__ float g_q[BT_TOTAL * C_DIM];    // 256 MiB
__device__ float g_k[BT_TOTAL * C_DIM];
__device__ float g_v[BT_TOTAL * C_DIM];
__device__ float g_ctx[BT_TOTAL * C_DIM];

// ---------------------------------------------------------------------------
// Helpers
// ---------------------------------------------------------------------------
__device__ __forceinline__ uint32_t smem_u32(const void* p) {
    uint32_t a;
    asm("{ .reg .u64 t; cvta.to.shared.u64 t, %1; cvt.u32.u64 %0, t; }" : "=r"(a) : "l"(p));
    return a;
}
__device__ __forceinline__ float f2tf32(float x) {
    uint32_t u;
    asm("cvt.rna.tf32.f32 %0, %1;" : "=r"(u) : "f"(x));
    return __uint_as_float(u);
}

__device__ __forceinline__ void mma_tf32(float* d, const uint32_t* a, const uint32_t* b) {
    asm volatile(
        "mma.sync.aligned.m16n8k8.row.col.f32.tf32.tf32.f32 "
        "{%0,%1,%2,%3}, {%4,%5,%6,%7}, {%8,%9}, {%0,%1,%2,%3};\n"
        : "+f"(d[0]), "+f"(d[1]), "+f"(d[2]), "+f"(d[3])
        : "r"(a[0]), "r"(a[1]), "r"(a[2]), "r"(a[3]),
          "r"(b[0]), "r"(b[1]));
}

// ---------------------------------------------------------------------------
// TF32 GEMM:  C[m,n] = sum_k A[m,k] * B[n,k]  (+ bias[n])
// M = gridDim.y*128, N = 512, K = 512.  Block 256 threads, tile 128x128x32.
// (FROZEN: measured at ~96% of the mma.sync tf32 ceiling.)
// ---------------------------------------------------------------------------
__global__ __launch_bounds__(256, 1)
void gemm_tf32_kernel(const float* __restrict__ A, const float* __restrict__ B,
                      float* __restrict__ Cout, const float* __restrict__ bias) {
    constexpr int K = 512;
    constexpr int N = 512;
    constexpr int LDS = 36;                 // padded stride (floats)
    constexpr int BUF = 128 * LDS;          // one tile buffer

    extern __shared__ float smem[];
    float* As = smem;                       // [2][128][36]
    float* Bs = smem + 2 * BUF;             // [2][128][36]

    const int tid   = threadIdx.x;
    const int lane  = tid & 31;
    const int warp  = tid >> 5;
    const int warpM = warp >> 2;            // 0..1  (64-row slab)
    const int warpN = warp & 3;             // 0..3  (32-col slab)
    const int gid   = lane >> 2;            // 0..7
    const int tig   = lane & 3;             // 0..3

    const int bm = blockIdx.y;
    const int bn = blockIdx.x;

    const float* Ag = A + (size_t)bm * 128 * K;
    const float* Bg = B + (size_t)bn * 128 * K;

    const int lrow = tid >> 3;              // 0..31
    const int lcol = (tid & 7) << 2;        // 0,4,...,28

    float4 aR[4], bR[4];
    float acc[4][4][4];
    #pragma unroll
    for (int i = 0; i < 4; ++i)
        #pragma unroll
        for (int j = 0; j < 4; ++j)
            #pragma unroll
            for (int r = 0; r < 4; ++r) acc[i][j][r] = 0.f;

    #define G2R(kt)                                                              \
        {                                                                        \
            const float* ap = Ag + (size_t)lrow * K + (kt) * 32 + lcol;          \
            const float* bp = Bg + (size_t)lrow * K + (kt) * 32 + lcol;          \
            _Pragma("unroll")                                                    \
            for (int r = 0; r < 4; ++r) {                                        \
                aR[r] = *(const float4*)(ap + (size_t)r * 32 * K);               \
                bR[r] = *(const float4*)(bp + (size_t)r * 32 * K);               \
            }                                                                    \
        }

    #define R2S(buf)                                                             \
        {                                                                        \
            float* as = As + (buf) * BUF;                                        \
            float* bs = Bs + (buf) * BUF;                                        \
            _Pragma("unroll")                                                    \
            for (int r = 0; r < 4; ++r) {                                        \
                int row = lrow + r * 32;                                         \
                float4 av = make_float4(f2tf32(aR[r].x), f2tf32(aR[r].y),        \
                                        f2tf32(aR[r].z), f2tf32(aR[r].w));       \
                float4 bv = make_float4(f2tf32(bR[r].x), f2tf32(bR[r].y),        \
                                        f2tf32(bR[r].z), f2tf32(bR[r].w));       \
                *(float4*)(as + row * LDS + lcol) = av;                          \
                *(float4*)(bs + row * LDS + lcol) = bv;                          \
            }                                                                    \
        }

    G2R(0);
    R2S(0);
    __syncthreads();

    #pragma unroll 1
    for (int kt = 0; kt < 16; ++kt) {
        const int cur = kt & 1;
        if (kt + 1 < 16) G2R(kt + 1);

        const float* as = As + cur * BUF;
        const float* bs = Bs + cur * BUF;
        #pragma unroll
        for (int ks = 0; ks < 4; ++ks) {
            const int kb = ks * 8;
            uint32_t aF[4][4];
            uint32_t bF[4][2];
            #pragma unroll
            for (int mt = 0; mt < 4; ++mt) {
                const int rb = warpM * 64 + mt * 16;
                aF[mt][0] = __float_as_uint(as[(rb + gid)     * LDS + kb + tig]);
                aF[mt][1] = __float_as_uint(as[(rb + gid + 8) * LDS + kb + tig]);
                aF[mt][2] = __float_as_uint(as[(rb + gid)     * LDS + kb + tig + 4]);
                aF[mt][3] = __float_as_uint(as[(rb + gid + 8) * LDS + kb + tig + 4]);
            }
            #pragma unroll
            for (int nt = 0; nt < 4; ++nt) {
                const int cb = warpN * 32 + nt * 8;
                bF[nt][0] = __float_as_uint(bs[(cb + gid) * LDS + kb + tig]);
                bF[nt][1] = __float_as_uint(bs[(cb + gid) * LDS + kb + tig + 4]);
            }
            #pragma unroll
            for (int mt = 0; mt < 4; ++mt)
                #pragma unroll
                for (int nt = 0; nt < 4; ++nt)
                    mma_tf32(acc[mt][nt], aF[mt], bF[nt]);
        }

        if (kt + 1 < 16) R2S((kt + 1) & 1);
        __syncthreads();
    }

    const size_t cbase = (size_t)bm * 128 * N + (size_t)bn * 128;
    #pragma unroll
    for (int mt = 0; mt < 4; ++mt) {
        const int r0 = warpM * 64 + mt * 16 + gid;
        #pragma unroll
        for (int nt = 0; nt < 4; ++nt) {
            const int c0 = warpN * 32 + nt * 8 + tig * 2;
            float b0 = 0.f, b1 = 0.f;
            if (bias) { b0 = bias[bn * 128 + c0]; b1 = bias[bn * 128 + c0 + 1]; }
            size_t o = cbase + (size_t)r0 * N + c0;
            float2 lo = make_float2(acc[mt][nt][0] + b0, acc[mt][nt][1] + b1);
            float2 hi = make_float2(acc[mt][nt][2] + b0, acc[mt][nt][3] + b1);
            *(float2*)(Cout + o)         = lo;
            *(float2*)(Cout + o + 8 * N) = hi;
        }
    }
    #undef G2R
    #undef R2S
}

// ---------------------------------------------------------------------------
// Fused attention middle: CTA per batch.
//   m = LN(mask[b]); sym = (m m^T)/sqrt(C), zero diag
//   sim[h,i,j] = (q_i . k_j)/8 + sym[i,j]*beta[h]; softmax over j
//   ctx[i, h*64+d] = sum_j attn[h,i,j] * v[j, h*64+d]
// Register-tiled: q reused across 8 j's per thread; v held in 16 regs per
// output column with all 16 i's computed per thread.
// ---------------------------------------------------------------------------
__global__ __launch_bounds__(256, 3)
void attn_kernel(const float* __restrict__ mask,
                 const float* __restrict__ ln_g, const float* __restrict__ ln_b,
                 const float* __restrict__ beta) {
    constexpr int PADC = 516;
    extern __shared__ float sm[];
    float* sM   = sm;                   // 16*516
    float* sK   = sM + 16 * PADC;       // 16*516
    float* sSym = sK + 16 * PADC;       // 256
    float* sSim = sSym + 256;           // 2048  [h][i][j]

    const int tid  = threadIdx.x;
    const int warp = tid >> 5;
    const int lane = tid & 31;
    const size_t base = (size_t)blockIdx.x * 8192;

    // --- async prefetch k -> sK (overlaps LN + sym) ---
    {
        const uint32_t skb = smem_u32(sK);
        const float* kg = g_k + base;
        #pragma unroll
        for (int r = 0; r < 8; ++r) {
            int f = tid + 256 * r;               // float4 index 0..2047
            int row = f >> 7, c4 = f & 127;
            uint32_t dst = skb + (uint32_t)(row * PADC + c4 * 4) * 4u;
            const float* src = kg + (size_t)row * 512 + c4 * 4;
            asm volatile("cp.async.ca.shared.global [%0], [%1], 16;" :: "r"(dst), "l"(src));
        }
        asm volatile("cp.async.commit_group;" ::: "memory");
    }

    // --- layernorm(mask) -> sM : warp per row, 2 rows/warp ---
    #pragma unroll
    for (int p = 0; p < 2; ++p) {
        const int r = warp + p * 8;
        const float4* mg = (const float4*)(mask + base + (size_t)r * 512);
        float4 vv[4];
        float s = 0.f, sq = 0.f;
        #pragma unroll
        for (int u = 0; u < 4; ++u) {
            vv[u] = mg[lane + 32 * u];
            s  += vv[u].x + vv[u].y + vv[u].z + vv[u].w;
            sq += vv[u].x * vv[u].x + vv[u].y * vv[u].y + vv[u].z * vv[u].z + vv[u].w * vv[u].w;
        }
        #pragma unroll
        for (int o = 16; o; o >>= 1) {
            s  += __shfl_xor_sync(0xffffffffu, s,  o);
            sq += __shfl_xor_sync(0xffffffffu, sq, o);
        }
        const float mu  = s * (1.f / 512.f);
        const float inv = rsqrtf(sq * (1.f / 512.f) - mu * mu + 1e-5f);
        float4* mr = (float4*)(sM + r * PADC);
        const float4* gg = (const float4*)ln_g;
        const float4* bv = (const float4*)ln_b;
        #pragma unroll
        for (int u = 0; u < 4; ++u) {
            float4 g4 = gg[lane + 32 * u], b4 = bv[lane + 32 * u];
            mr[lane + 32 * u] = make_float4((vv[u].x - mu) * inv * g4.x + b4.x,
                                            (vv[u].y - mu) * inv * g4.y + b4.y,
                                            (vv[u].z - mu) * inv * g4.z + b4.z,
                                            (vv[u].w - mu) * inv * g4.w + b4.w);
        }
    }
    __syncthreads();

    // --- sym = (m m^T)/sqrt(C), zero diagonal: one thread per (i,j) ---
    {
        const int i = tid >> 4, j = tid & 15;
        const float4* mi = (const float4*)(sM + i * PADC);
        const float4* mj = (const float4*)(sM + j * PADC);
        float s = 0.f;
        #pragma unroll 8
        for (int c = 0; c < 128; ++c) {
            float4 a = mi[c], b = mj[c];
            s += a.x * b.x + a.y * b.y + a.z * b.z + a.w * b.w;
        }
        sSym[tid] = (i == j) ? 0.f : s * 0.044194173824159216f;  // 1/sqrt(512)
    }
    asm volatile("cp.async.wait_group 0;" ::: "memory");
    __syncthreads();

    // --- sim[h,i,j] = q_i.k_j/8 + sym*beta[h] ---
    // thread -> fixed (h,i) + 8 j's; q float4 loaded once per c, reused x8
    {
        const int pair  = tid >> 1;              // 0..127 = h*16+i
        const int h     = pair >> 4;
        const int i     = pair & 15;
        const int jbase = (tid & 1) * 8;

        const float4* qp = (const float4*)(g_q + base + (size_t)i * 512 + h * 64);
        const float*  kb = sK + jbase * PADC + h * 64;

        float s[8];
        #pragma unroll
        for (int jj = 0; jj < 8; ++jj) s[jj] = 0.f;

        #pragma unroll
        for (int c = 0; c < 16; ++c) {
            const float4 q4 = qp[c];
            #pragma unroll
            for (int jj = 0; jj < 8; ++jj) {
                const float4 k4 = *(const float4*)(kb + jj * PADC + c * 4);
                s[jj] += q4.x * k4.x + q4.y * k4.y + q4.z * k4.z + q4.w * k4.w;
            }
        }
        const float bh = beta[h];
        float*       dst  = sSim + pair * 16 + jbase;
        const float* symr = sSym + i * 16 + jbase;
        #pragma unroll
        for (int jj = 0; jj < 8; ++jj)
            dst[jj] = s[jj] * 0.125f + symr[jj] * bh;
    }
    __syncthreads();

    // --- softmax over j: one thread per (h,i) row ---
    if (tid < 128) {
        float* row = sSim + tid * 16;
        float mx = row[0];
        #pragma unroll
        for (int j = 1; j < 16; ++j) mx = fmaxf(mx, row[j]);
        float s = 0.f;
        #pragma unroll
        for (int j = 0; j < 16; ++j) { float e = __expf(row[j] - mx); row[j] = e; s += e; }
        const float inv = 1.f / s;
        #pragma unroll
        for (int j = 0; j < 16; ++j) row[j] *= inv;
    }
    __syncthreads();

    // --- ctx = attn @ v : thread owns column e, v[0..15][e] in registers,
    //     computes all 16 i outputs (v traffic /16; stores coalesced) ---
    {
        const float* vg = g_v + base;
        #pragma unroll
        for (int half = 0; half < 2; ++half) {
            const int e = tid + half * 256;
            const int h = e >> 6;                 // warp-uniform
            float vr[16];
            #pragma unroll
            for (int j = 0; j < 16; ++j) vr[j] = vg[(size_t)j * 512 + e];
            const float* ab = sSim + h * 256;     // [i][j] for this head
            #pragma unroll
            for (int i = 0; i < 16; ++i) {
                const float* ar = ab + i * 16;    // broadcast LDS (h uniform)
                float acc = 0.f;
                #pragma unroll
                for (int j = 0; j < 16; ++j) acc += ar[j] * vr[j];
                g_ctx[base + (size_t)i * 512 + e] = acc;
            }
        }
    }
}

// ---------------------------------------------------------------------------
// Launch
// ---------------------------------------------------------------------------
extern "C" void kernel_launch(void* const* d_in, const int* in_sizes, int n_in,
                              void* d_out, int out_size) {
    const float* x    = (const float*)d_in[0];
    const float* mask = (const float*)d_in[1];
    const float* w_q  = (const float*)d_in[2];
    const float* w_k  = (const float*)d_in[3];
    const float* w_v  = (const float*)d_in[4];
    const float* w_o  = (const float*)d_in[5];
    const float* b_o  = (const float*)d_in[6];
    const float* beta = (const float*)d_in[7];
    const float* ln_g = (const float*)d_in[8];
    const float* ln_b = (const float*)d_in[9];
    float* out = (float*)d_out;

    float *q, *k, *v, *ctx;
    cudaGetSymbolAddress((void**)&q,   g_q);
    cudaGetSymbolAddress((void**)&k,   g_k);
    cudaGetSymbolAddress((void**)&v,   g_v);
    cudaGetSymbolAddress((void**)&ctx, g_ctx);

    const int bt = in_sizes[0] / C_DIM;       // B*T = 131072
    const int bb = bt / 16;                   // B   = 8192

    const int gemm_smem = 2 * 2 * 128 * 36 * 4;              // 73728
    const int attn_smem = (2 * 16 * 516 + 256 + 2048) * 4;   // 75264
    cudaFuncSetAttribute(gemm_tf32_kernel, cudaFuncAttributeMaxDynamicSharedMemorySize, gemm_smem);
    cudaFuncSetAttribute(attn_kernel,      cudaFuncAttributeMaxDynamicSharedMemorySize, attn_smem);

    dim3 grid(4, bt / 128);                   // N/128 x M/128
    gemm_tf32_kernel<<<grid, 256, gemm_smem>>>(x,   w_q, q,   nullptr);
    gemm_tf32_kernel<<<grid, 256, gemm_smem>>>(x,   w_k, k,   nullptr);
    gemm_tf32_kernel<<<grid, 256, gemm_smem>>>(x,   w_v, v,   nullptr);
    attn_kernel<<<bb, 256, attn_smem>>>(mask, ln_g, ln_b, beta);
    gemm_tf32_kernel<<<grid, 256, gemm_smem>>>(ctx, w_o, out, b_o);
}

// round 7
// speedup vs baseline: 2.0132x; 1.7700x over previous
#include <cuda_runtime.h>
#include <cuda_fp16.h>
#include <cstdint>
#include <cstddef>

// Problem shape (fixed by the dataset): B=8192, T=16, C=512, H=8, DH=64
#define BT_TOTAL 131072          // B*T
#define B_TOTAL  8192
#define C_DIM    512

// ---------------------------------------------------------------------------
// Scratch (device globals; no allocations allowed)
// ---------------------------------------------------------------------------
__device__ float g_q[BT_TOTAL * C_DIM];    // 256 MiB
__device__ float g_k[BT_TOTAL * C_DIM];
__device__ float g_v[BT_TOTAL * C_DIM];
__device__ float g_ctx[BT_TOTAL * C_DIM];

// ---------------------------------------------------------------------------
// Helpers
// ---------------------------------------------------------------------------
__device__ __forceinline__ uint32_t smem_u32(const void* p) {
    uint32_t a;
    asm("{ .reg .u64 t; cvta.to.shared.u64 t, %1; cvt.u32.u64 %0, t; }" : "=r"(a) : "l"(p));
    return a;
}
__device__ __forceinline__ float f2tf32(float x) {
    uint32_t u;
    asm("cvt.rna.tf32.f32 %0, %1;" : "=r"(u) : "f"(x));
    return __uint_as_float(u);
}
__device__ __forceinline__ uint32_t h2b(__half2 h) {
    return *reinterpret_cast<uint32_t*>(&h);
}

__device__ __forceinline__ void mma_tf32(float* d, const uint32_t* a, const uint32_t* b) {
    asm volatile(
        "mma.sync.aligned.m16n8k8.row.col.f32.tf32.tf32.f32 "
        "{%0,%1,%2,%3}, {%4,%5,%6,%7}, {%8,%9}, {%0,%1,%2,%3};\n"
        : "+f"(d[0]), "+f"(d[1]), "+f"(d[2]), "+f"(d[3])
        : "r"(a[0]), "r"(a[1]), "r"(a[2]), "r"(a[3]),
          "r"(b[0]), "r"(b[1]));
}
__device__ __forceinline__ void mma_f16(float* d, const uint32_t* a, const uint32_t* b) {
    asm volatile(
        "mma.sync.aligned.m16n8k16.row.col.f32.f16.f16.f32 "
        "{%0,%1,%2,%3}, {%4,%5,%6,%7}, {%8,%9}, {%0,%1,%2,%3};\n"
        : "+f"(d[0]), "+f"(d[1]), "+f"(d[2]), "+f"(d[3])
        : "r"(a[0]), "r"(a[1]), "r"(a[2]), "r"(a[3]),
          "r"(b[0]), "r"(b[1]));
}

// ---------------------------------------------------------------------------
// FP16 GEMM:  C[m,n] = sum_k A[m,k] * B[n,k]  (+ bias[n])
// fp16 has the same 10 mantissa bits as tf32 but 2x the mma throughput.
// M = gridDim.y*128, N = 512, K = 512. Block 256 threads, tile 128x128x32.
// ---------------------------------------------------------------------------
__global__ __launch_bounds__(256, 2)
void gemm_f16_kernel(const float* __restrict__ A, const float* __restrict__ B,
                     float* __restrict__ Cout, const float* __restrict__ bias) {
    constexpr int K = 512;
    constexpr int N = 512;
    constexpr int LDSH = 40;                // padded stride (halves)
    constexpr int BUFH = 128 * LDSH;        // one tile buffer (halves)

    extern __shared__ __half hsm[];
    __half* As = hsm;                       // [2][128][40]
    __half* Bs = hsm + 2 * BUFH;            // [2][128][40]

    const int tid   = threadIdx.x;
    const int lane  = tid & 31;
    const int warp  = tid >> 5;
    const int warpM = warp >> 2;            // 0..1
    const int warpN = warp & 3;             // 0..3
    const int gid   = lane >> 2;            // 0..7
    const int tig   = lane & 3;             // 0..3

    const int bm = blockIdx.y;
    const int bn = blockIdx.x;

    const float* Ag = A + (size_t)bm * 128 * K;
    const float* Bg = B + (size_t)bn * 128 * K;

    const int lrow = tid >> 3;              // 0..31
    const int lcol = (tid & 7) << 2;        // 0,4,...,28

    float4 aR[4], bR[4];
    float acc[4][4][4];
    #pragma unroll
    for (int i = 0; i < 4; ++i)
        #pragma unroll
        for (int j = 0; j < 4; ++j)
            #pragma unroll
            for (int r = 0; r < 4; ++r) acc[i][j][r] = 0.f;

    #define G2R(kt)                                                              \
        {                                                                        \
            const float* ap = Ag + (size_t)lrow * K + (kt) * 32 + lcol;          \
            const float* bp = Bg + (size_t)lrow * K + (kt) * 32 + lcol;          \
            _Pragma("unroll")                                                    \
            for (int r = 0; r < 4; ++r) {                                        \
                aR[r] = *(const float4*)(ap + (size_t)r * 32 * K);               \
                bR[r] = *(const float4*)(bp + (size_t)r * 32 * K);               \
            }                                                                    \
        }

    #define R2S(buf)                                                             \
        {                                                                        \
            __half* as = As + (buf) * BUFH;                                      \
            __half* bs = Bs + (buf) * BUFH;                                      \
            _Pragma("unroll")                                                    \
            for (int r = 0; r < 4; ++r) {                                        \
                int row = lrow + r * 32;                                         \
                uint2 ua = make_uint2(h2b(__floats2half2_rn(aR[r].x, aR[r].y)),  \
                                      h2b(__floats2half2_rn(aR[r].z, aR[r].w))); \
                uint2 ub = make_uint2(h2b(__floats2half2_rn(bR[r].x, bR[r].y)),  \
                                      h2b(__floats2half2_rn(bR[r].z, bR[r].w))); \
                *(uint2*)(as + row * LDSH + lcol) = ua;                          \
                *(uint2*)(bs + row * LDSH + lcol) = ub;                          \
            }                                                                    \
        }

    G2R(0);
    R2S(0);
    __syncthreads();

    #pragma unroll 1
    for (int kt = 0; kt < 16; ++kt) {
        const int cur = kt & 1;
        if (kt + 1 < 16) G2R(kt + 1);

        const __half* as = As + cur * BUFH;
        const __half* bs = Bs + cur * BUFH;
        #pragma unroll
        for (int ks = 0; ks < 2; ++ks) {
            const int kb = ks * 16 + tig * 2;
            uint32_t aF[4][4];
            uint32_t bF[4][2];
            #pragma unroll
            for (int mt = 0; mt < 4; ++mt) {
                const int rb = warpM * 64 + mt * 16;
                aF[mt][0] = *(const uint32_t*)(as + (rb + gid)     * LDSH + kb);
                aF[mt][1] = *(const uint32_t*)(as + (rb + gid + 8) * LDSH + kb);
                aF[mt][2] = *(const uint32_t*)(as + (rb + gid)     * LDSH + kb + 8);
                aF[mt][3] = *(const uint32_t*)(as + (rb + gid + 8) * LDSH + kb + 8);
            }
            #pragma unroll
            for (int nt = 0; nt < 4; ++nt) {
                const int cb = warpN * 32 + nt * 8;
                bF[nt][0] = *(const uint32_t*)(bs + (cb + gid) * LDSH + kb);
                bF[nt][1] = *(const uint32_t*)(bs + (cb + gid) * LDSH + kb + 8);
            }
            #pragma unroll
            for (int mt = 0; mt < 4; ++mt)
                #pragma unroll
                for (int nt = 0; nt < 4; ++nt)
                    mma_f16(acc[mt][nt], aF[mt], bF[nt]);
        }

        if (kt + 1 < 16) R2S((kt + 1) & 1);
        __syncthreads();
    }

    const size_t cbase = (size_t)bm * 128 * N + (size_t)bn * 128;
    #pragma unroll
    for (int mt = 0; mt < 4; ++mt) {
        const int r0 = warpM * 64 + mt * 16 + gid;
        #pragma unroll
        for (int nt = 0; nt < 4; ++nt) {
            const int c0 = warpN * 32 + nt * 8 + tig * 2;
            float b0 = 0.f, b1 = 0.f;
            if (bias) { b0 = bias[bn * 128 + c0]; b1 = bias[bn * 128 + c0 + 1]; }
            size_t o = cbase + (size_t)r0 * N + c0;
            float2 lo = make_float2(acc[mt][nt][0] + b0, acc[mt][nt][1] + b1);
            float2 hi = make_float2(acc[mt][nt][2] + b0, acc[mt][nt][3] + b1);
            *(float2*)(Cout + o)         = lo;
            *(float2*)(Cout + o + 8 * N) = hi;
        }
    }
    #undef G2R
    #undef R2S
}

// ---------------------------------------------------------------------------
// Fused attention middle: CTA per batch. sym and sim via tf32 mma.sync.
//   m = LN(mask[b]) (tf32-rounded); sym = (m m^T)/sqrt(C), zero diag
//   sim[h,i,j] = (q_i . k_j)/8 + sym[i,j]*beta[h]; softmax over j
//   ctx[i, h*64+d] = sum_j attn[h,i,j] * v[j, h*64+d]
// ---------------------------------------------------------------------------
__global__ __launch_bounds__(256, 2)
void attn_kernel(const float* __restrict__ mask,
                 const float* __restrict__ ln_g, const float* __restrict__ ln_b,
                 const float* __restrict__ beta) {
    constexpr int PADC = 516;
    extern __shared__ float sm[];
    float* sM   = sm;                   // 16*516 (LN output, tf32-rounded)
    float* sQ   = sM + 16 * PADC;       // 16*516
    float* sK   = sQ + 16 * PADC;       // 16*516
    float* sSym = sK + 16 * PADC;       // 256
    float* sSim = sSym + 256;           // 2048  [h][i][j]

    const int tid  = threadIdx.x;
    const int warp = tid >> 5;
    const int lane = tid & 31;
    const int gid  = lane >> 2;         // 0..7
    const int tig  = lane & 3;          // 0..3
    const size_t base = (size_t)blockIdx.x * 8192;

    // --- async prefetch q,k -> smem (overlaps LN + sym) ---
    {
        const uint32_t sqb = smem_u32(sQ);
        const uint32_t skb = smem_u32(sK);
        const float* qg = g_q + base;
        const float* kg = g_k + base;
        #pragma unroll
        for (int r = 0; r < 8; ++r) {
            int f = tid + 256 * r;               // float4 index 0..2047
            int row = f >> 7, c4 = f & 127;
            uint32_t off = (uint32_t)(row * PADC + c4 * 4) * 4u;
            const float* qs = qg + (size_t)row * 512 + c4 * 4;
            const float* ks = kg + (size_t)row * 512 + c4 * 4;
            asm volatile("cp.async.ca.shared.global [%0], [%1], 16;" :: "r"(sqb + off), "l"(qs));
            asm volatile("cp.async.ca.shared.global [%0], [%1], 16;" :: "r"(skb + off), "l"(ks));
        }
        asm volatile("cp.async.commit_group;" ::: "memory");
    }

    // --- layernorm(mask) -> sM (tf32-rounded): warp per row, 2 rows/warp ---
    #pragma unroll
    for (int p = 0; p < 2; ++p) {
        const int r = warp + p * 8;
        const float4* mg = (const float4*)(mask + base + (size_t)r * 512);
        float4 vv[4];
        float s = 0.f, sq = 0.f;
        #pragma unroll
        for (int u = 0; u < 4; ++u) {
            vv[u] = mg[lane + 32 * u];
            s  += vv[u].x + vv[u].y + vv[u].z + vv[u].w;
            sq += vv[u].x * vv[u].x + vv[u].y * vv[u].y + vv[u].z * vv[u].z + vv[u].w * vv[u].w;
        }
        #pragma unroll
        for (int o = 16; o; o >>= 1) {
            s  += __shfl_xor_sync(0xffffffffu, s,  o);
            sq += __shfl_xor_sync(0xffffffffu, sq, o);
        }
        const float mu  = s * (1.f / 512.f);
        const float inv = rsqrtf(sq * (1.f / 512.f) - mu * mu + 1e-5f);
        float4* mr = (float4*)(sM + r * PADC);
        const float4* gg = (const float4*)ln_g;
        const float4* bv = (const float4*)ln_b;
        #pragma unroll
        for (int u = 0; u < 4; ++u) {
            float4 g4 = gg[lane + 32 * u], b4 = bv[lane + 32 * u];
            mr[lane + 32 * u] = make_float4(f2tf32((vv[u].x - mu) * inv * g4.x + b4.x),
                                            f2tf32((vv[u].y - mu) * inv * g4.y + b4.y),
                                            f2tf32((vv[u].z - mu) * inv * g4.z + b4.z),
                                            f2tf32((vv[u].w - mu) * inv * g4.w + b4.w));
        }
    }
    __syncthreads();

    // --- sym = (m m^T)/sqrt(C) via tf32 mma: warps 0,1 (n-halves) ---
    if (warp < 2) {
        float acc4[4] = {0.f, 0.f, 0.f, 0.f};
        const int nb = warp * 8;
        #pragma unroll 4
        for (int k8 = 0; k8 < 64; ++k8) {
            const int kb = k8 * 8 + tig;
            uint32_t aF[4], bF[2];
            aF[0] = __float_as_uint(sM[gid * PADC + kb]);
            aF[1] = __float_as_uint(sM[(gid + 8) * PADC + kb]);
            aF[2] = __float_as_uint(sM[gid * PADC + kb + 4]);
            aF[3] = __float_as_uint(sM[(gid + 8) * PADC + kb + 4]);
            bF[0] = __float_as_uint(sM[(nb + gid) * PADC + kb]);
            bF[1] = __float_as_uint(sM[(nb + gid) * PADC + kb + 4]);
            mma_tf32(acc4, aF, bF);
        }
        const float S = 0.044194173824159216f;  // 1/sqrt(512)
        const int cc = nb + tig * 2;
        sSym[gid * 16 + cc]           = (gid == cc)         ? 0.f : acc4[0] * S;
        sSym[gid * 16 + cc + 1]       = (gid == cc + 1)     ? 0.f : acc4[1] * S;
        sSym[(gid + 8) * 16 + cc]     = (gid + 8 == cc)     ? 0.f : acc4[2] * S;
        sSym[(gid + 8) * 16 + cc + 1] = (gid + 8 == cc + 1) ? 0.f : acc4[3] * S;
    }
    asm volatile("cp.async.wait_group 0;" ::: "memory");
    __syncthreads();

    // --- sim[h] = q_h k_h^T /8 + sym*beta[h] via tf32 mma: warp h ---
    {
        const int hb = warp * 64;
        const float bh = beta[warp];
        float acc8[2][4];
        #pragma unroll
        for (int nt = 0; nt < 2; ++nt)
            #pragma unroll
            for (int r = 0; r < 4; ++r) acc8[nt][r] = 0.f;

        #pragma unroll
        for (int k8 = 0; k8 < 8; ++k8) {
            const int kb = hb + k8 * 8 + tig;
            uint32_t aF[4], bF[2];
            aF[0] = __float_as_uint(sQ[gid * PADC + kb]);
            aF[1] = __float_as_uint(sQ[(gid + 8) * PADC + kb]);
            aF[2] = __float_as_uint(sQ[gid * PADC + kb + 4]);
            aF[3] = __float_as_uint(sQ[(gid + 8) * PADC + kb + 4]);
            #pragma unroll
            for (int nt = 0; nt < 2; ++nt) {
                bF[0] = __float_as_uint(sK[(nt * 8 + gid) * PADC + kb]);
                bF[1] = __float_as_uint(sK[(nt * 8 + gid) * PADC + kb + 4]);
                mma_tf32(acc8[nt], aF, bF);
            }
        }
        float* simh = sSim + warp * 256;
        #pragma unroll
        for (int nt = 0; nt < 2; ++nt) {
            const int c0 = nt * 8 + tig * 2;
            simh[gid * 16 + c0]           = acc8[nt][0] * 0.125f + sSym[gid * 16 + c0] * bh;
            simh[gid * 16 + c0 + 1]       = acc8[nt][1] * 0.125f + sSym[gid * 16 + c0 + 1] * bh;
            simh[(gid + 8) * 16 + c0]     = acc8[nt][2] * 0.125f + sSym[(gid + 8) * 16 + c0] * bh;
            simh[(gid + 8) * 16 + c0 + 1] = acc8[nt][3] * 0.125f + sSym[(gid + 8) * 16 + c0 + 1] * bh;
        }
    }
    __syncthreads();

    // --- softmax over j: one thread per (h,i) row ---
    if (tid < 128) {
        float* row = sSim + tid * 16;
        float mx = row[0];
        #pragma unroll
        for (int j = 1; j < 16; ++j) mx = fmaxf(mx, row[j]);
        float s = 0.f;
        #pragma unroll
        for (int j = 0; j < 16; ++j) { float e = __expf(row[j] - mx); row[j] = e; s += e; }
        const float inv = 1.f / s;
        #pragma unroll
        for (int j = 0; j < 16; ++j) row[j] *= inv;
    }
    __syncthreads();

    // --- ctx = attn @ v : thread owns column e, v in 16 regs ---
    {
        const float* vg = g_v + base;
        #pragma unroll
        for (int half = 0; half < 2; ++half) {
            const int e = tid + half * 256;
            const int h = e >> 6;                 // warp-uniform
            float vr[16];
            #pragma unroll
            for (int j = 0; j < 16; ++j) vr[j] = vg[(size_t)j * 512 + e];
            const float* ab = sSim + h * 256;
            #pragma unroll
            for (int i = 0; i < 16; ++i) {
                const float* ar = ab + i * 16;    // broadcast LDS
                float acc = 0.f;
                #pragma unroll
                for (int j = 0; j < 16; ++j) acc += ar[j] * vr[j];
                g_ctx[base + (size_t)i * 512 + e] = acc;
            }
        }
    }
}

// ---------------------------------------------------------------------------
// Launch
// ---------------------------------------------------------------------------
extern "C" void kernel_launch(void* const* d_in, const int* in_sizes, int n_in,
                              void* d_out, int out_size) {
    const float* x    = (const float*)d_in[0];
    const float* mask = (const float*)d_in[1];
    const float* w_q  = (const float*)d_in[2];
    const float* w_k  = (const float*)d_in[3];
    const float* w_v  = (const float*)d_in[4];
    const float* w_o  = (const float*)d_in[5];
    const float* b_o  = (const float*)d_in[6];
    const float* beta = (const float*)d_in[7];
    const float* ln_g = (const float*)d_in[8];
    const float* ln_b = (const float*)d_in[9];
    float* out = (float*)d_out;

    float *q, *k, *v, *ctx;
    cudaGetSymbolAddress((void**)&q,   g_q);
    cudaGetSymbolAddress((void**)&k,   g_k);
    cudaGetSymbolAddress((void**)&v,   g_v);
    cudaGetSymbolAddress((void**)&ctx, g_ctx);

    const int bt = in_sizes[0] / C_DIM;       // B*T = 131072
    const int bb = bt / 16;                   // B   = 8192

    const int gemm_smem = 2 * 2 * 128 * 40 * 2;                       // 40960
    const int attn_smem = (3 * 16 * 516 + 256 + 2048) * 4;            // 108288
    cudaFuncSetAttribute(gemm_f16_kernel, cudaFuncAttributeMaxDynamicSharedMemorySize, gemm_smem);
    cudaFuncSetAttribute(attn_kernel,     cudaFuncAttributeMaxDynamicSharedMemorySize, attn_smem);

    dim3 grid(4, bt / 128);                   // N/128 x M/128
    gemm_f16_kernel<<<grid, 256, gemm_smem>>>(x,   w_q, q,   nullptr);
    gemm_f16_kernel<<<grid, 256, gemm_smem>>>(x,   w_k, k,   nullptr);
    gemm_f16_kernel<<<grid, 256, gemm_smem>>>(x,   w_v, v,   nullptr);
    attn_kernel<<<bb, 256, attn_smem>>>(mask, ln_g, ln_b, beta);
    gemm_f16_kernel<<<grid, 256, gemm_smem>>>(ctx, w_o, out, b_o);
}

// round 9
// speedup vs baseline: 2.1564x; 1.0712x over previous
#include <cuda_runtime.h>
#include <cuda_fp16.h>
#include <cstdint>
#include <cstddef>

// Problem shape (fixed by the dataset): B=8192, T=16, C=512, H=8, DH=64
#define BT_TOTAL 131072          // B*T
#define B_TOTAL  8192
#define C_DIM    512

// ---------------------------------------------------------------------------
// Scratch (device globals; no allocations allowed)
// q,k,ctx in fp16 (identical rounding to what downstream consumers already
// applied); v in fp32 (consumed exactly).
// ---------------------------------------------------------------------------
__device__ __half g_q[BT_TOTAL * C_DIM];     // 128 MiB
__device__ __half g_k[BT_TOTAL * C_DIM];
__device__ float  g_v[BT_TOTAL * C_DIM];     // 256 MiB
__device__ __half g_ctx[BT_TOTAL * C_DIM];

// ---------------------------------------------------------------------------
// Helpers
// ---------------------------------------------------------------------------
__device__ __forceinline__ uint32_t smem_u32(const void* p) {
    uint32_t a;
    asm("{ .reg .u64 t; cvta.to.shared.u64 t, %1; cvt.u32.u64 %0, t; }" : "=r"(a) : "l"(p));
    return a;
}
__device__ __forceinline__ float f2tf32(float x) {
    uint32_t u;
    asm("cvt.rna.tf32.f32 %0, %1;" : "=r"(u) : "f"(x));
    return __uint_as_float(u);
}
__device__ __forceinline__ uint32_t h2b(__half2 h) {
    return *reinterpret_cast<uint32_t*>(&h);
}

__device__ __forceinline__ void mma_tf32(float* d, const uint32_t* a, const uint32_t* b) {
    asm volatile(
        "mma.sync.aligned.m16n8k8.row.col.f32.tf32.tf32.f32 "
        "{%0,%1,%2,%3}, {%4,%5,%6,%7}, {%8,%9}, {%0,%1,%2,%3};\n"
        : "+f"(d[0]), "+f"(d[1]), "+f"(d[2]), "+f"(d[3])
        : "r"(a[0]), "r"(a[1]), "r"(a[2]), "r"(a[3]),
          "r"(b[0]), "r"(b[1]));
}
__device__ __forceinline__ void mma_f16(float* d, const uint32_t* a, const uint32_t* b) {
    asm volatile(
        "mma.sync.aligned.m16n8k16.row.col.f32.f16.f16.f32 "
        "{%0,%1,%2,%3}, {%4,%5,%6,%7}, {%8,%9}, {%0,%1,%2,%3};\n"
        : "+f"(d[0]), "+f"(d[1]), "+f"(d[2]), "+f"(d[3])
        : "r"(a[0]), "r"(a[1]), "r"(a[2]), "r"(a[3]),
          "r"(b[0]), "r"(b[1]));
}

// ---------------------------------------------------------------------------
// FP16-core GEMM:  C[m,n] = sum_k A[m,k] * B[n,k]  (+ bias[n])
// A_HALF: A is __half in gmem (loaded raw); else float (converted on stage).
// OUT_HALF: C is __half (no bias); else float (+ optional bias).
// M = gridDim.y*128, N = 512, K = 512. Block 256 threads, tile 128x128x32.
// ---------------------------------------------------------------------------
template<bool A_HALF, bool OUT_HALF>
__global__ __launch_bounds__(256, 2)
void gemm_kernel(const void* __restrict__ Av, const float* __restrict__ B,
                 void* __restrict__ Cv, const float* __restrict__ bias) {
    constexpr int K = 512;
    constexpr int N = 512;
    constexpr int LDSH = 40;                // padded stride (halves)
    constexpr int BUFH = 128 * LDSH;

    extern __shared__ __half hsm[];
    __half* As = hsm;                       // [2][128][40]
    __half* Bs = hsm + 2 * BUFH;            // [2][128][40]

    const int tid   = threadIdx.x;
    const int lane  = tid & 31;
    const int warp  = tid >> 5;
    const int warpM = warp >> 2;            // 0..1
    const int warpN = warp & 3;             // 0..3
    const int gid   = lane >> 2;            // 0..7
    const int tig   = lane & 3;             // 0..3

    const int bm = blockIdx.y;
    const int bn = blockIdx.x;

    const float*  Agf = (const float*) Av + (size_t)bm * 128 * K;
    const __half* Agh = (const __half*)Av + (size_t)bm * 128 * K;
    const float*  Bg  = B + (size_t)bn * 128 * K;

    const int lrow = tid >> 3;              // 0..31
    const int lcol = (tid & 7) << 2;        // 0,4,...,28

    float4 aR[4];
    uint2  aRh[4];
    float4 bR[4];
    float acc[4][4][4];
    #pragma unroll
    for (int i = 0; i < 4; ++i)
        #pragma unroll
        for (int j = 0; j < 4; ++j)
            #pragma unroll
            for (int r = 0; r < 4; ++r) acc[i][j][r] = 0.f;

    auto g2r = [&](int kt) {
        const float* bp = Bg + (size_t)lrow * K + kt * 32 + lcol;
        #pragma unroll
        for (int r = 0; r < 4; ++r) bR[r] = *(const float4*)(bp + (size_t)r * 32 * K);
        if (A_HALF) {
            const __half* ap = Agh + (size_t)lrow * K + kt * 32 + lcol;
            #pragma unroll
            for (int r = 0; r < 4; ++r) aRh[r] = *(const uint2*)(ap + (size_t)r * 32 * K);
        } else {
            const float* ap = Agf + (size_t)lrow * K + kt * 32 + lcol;
            #pragma unroll
            for (int r = 0; r < 4; ++r) aR[r] = *(const float4*)(ap + (size_t)r * 32 * K);
        }
    };
    auto r2s = [&](int buf) {
        __half* as = As + buf * BUFH;
        __half* bs = Bs + buf * BUFH;
        #pragma unroll
        for (int r = 0; r < 4; ++r) {
            int row = lrow + r * 32;
            if (A_HALF) {
                *(uint2*)(as + row * LDSH + lcol) = aRh[r];
            } else {
                uint2 ua = make_uint2(h2b(__floats2half2_rn(aR[r].x, aR[r].y)),
                                      h2b(__floats2half2_rn(aR[r].z, aR[r].w)));
                *(uint2*)(as + row * LDSH + lcol) = ua;
            }
            uint2 ub = make_uint2(h2b(__floats2half2_rn(bR[r].x, bR[r].y)),
                                  h2b(__floats2half2_rn(bR[r].z, bR[r].w)));
            *(uint2*)(bs + row * LDSH + lcol) = ub;
        }
    };

    g2r(0);
    r2s(0);
    __syncthreads();

    #pragma unroll 1
    for (int kt = 0; kt < 16; ++kt) {
        const int cur = kt & 1;
        if (kt + 1 < 16) g2r(kt + 1);

        const __half* as = As + cur * BUFH;
        const __half* bs = Bs + cur * BUFH;
        #pragma unroll
        for (int ks = 0; ks < 2; ++ks) {
            const int kb = ks * 16 + tig * 2;
            uint32_t aF[4][4];
            uint32_t bF[4][2];
            #pragma unroll
            for (int mt = 0; mt < 4; ++mt) {
                const int rb = warpM * 64 + mt * 16;
                aF[mt][0] = *(const uint32_t*)(as + (rb + gid)     * LDSH + kb);
                aF[mt][1] = *(const uint32_t*)(as + (rb + gid + 8) * LDSH + kb);
                aF[mt][2] = *(const uint32_t*)(as + (rb + gid)     * LDSH + kb + 8);
                aF[mt][3] = *(const uint32_t*)(as + (rb + gid + 8) * LDSH + kb + 8);
            }
            #pragma unroll
            for (int nt = 0; nt < 4; ++nt) {
                const int cb = warpN * 32 + nt * 8;
                bF[nt][0] = *(const uint32_t*)(bs + (cb + gid) * LDSH + kb);
                bF[nt][1] = *(const uint32_t*)(bs + (cb + gid) * LDSH + kb + 8);
            }
            #pragma unroll
            for (int mt = 0; mt < 4; ++mt)
                #pragma unroll
                for (int nt = 0; nt < 4; ++nt)
                    mma_f16(acc[mt][nt], aF[mt], bF[nt]);
        }

        if (kt + 1 < 16) r2s((kt + 1) & 1);
        __syncthreads();
    }

    const size_t cbase = (size_t)bm * 128 * N + (size_t)bn * 128;
    #pragma unroll
    for (int mt = 0; mt < 4; ++mt) {
        const int r0 = warpM * 64 + mt * 16 + gid;
        #pragma unroll
        for (int nt = 0; nt < 4; ++nt) {
            const int c0 = warpN * 32 + nt * 8 + tig * 2;
            size_t o = cbase + (size_t)r0 * N + c0;
            if (OUT_HALF) {
                __half* Ch = (__half*)Cv;
                *(__half2*)(Ch + o)         = __floats2half2_rn(acc[mt][nt][0], acc[mt][nt][1]);
                *(__half2*)(Ch + o + 8 * N) = __floats2half2_rn(acc[mt][nt][2], acc[mt][nt][3]);
            } else {
                float* Cf = (float*)Cv;
                float b0 = 0.f, b1 = 0.f;
                if (bias) { b0 = bias[bn * 128 + c0]; b1 = bias[bn * 128 + c0 + 1]; }
                *(float2*)(Cf + o)         = make_float2(acc[mt][nt][0] + b0, acc[mt][nt][1] + b1);
                *(float2*)(Cf + o + 8 * N) = make_float2(acc[mt][nt][2] + b0, acc[mt][nt][3] + b1);
            }
        }
    }
}

// ---------------------------------------------------------------------------
// Fused attention middle: CTA per batch.
//   m = LN(mask[b]) (tf32-rounded); sym = (m m^T)/sqrt(C) via tf32 mma
//   sim[h,i,j] = (q_i.k_j)/8 + sym*beta[h] via fp16 mma (q,k half in smem)
//   softmax; ctx = attn @ v (v fp32 in regs), ctx stored as fp16
// ---------------------------------------------------------------------------
__global__ __launch_bounds__(256, 3)
void attn_kernel(const float* __restrict__ mask,
                 const float* __restrict__ ln_g, const float* __restrict__ ln_b,
                 const float* __restrict__ beta) {
    constexpr int PADC = 516;   // fp32 row stride (floats)
    constexpr int PADH = 520;   // fp16 row stride (halves)
    extern __shared__ char smraw[];
    float*  sSym = (float*)(smraw);                  // 256 f   @ 0
    float*  sSim = (float*)(smraw + 1024);           // 2048 f  @ 1024
    __half* sQh  = (__half*)(smraw + 9216);          // 16*520 h
    __half* sKh  = (__half*)(smraw + 25856);         // 16*520 h
    float*  sM   = (float*)(smraw + 42496);          // 16*516 f   (end 75520)

    const int tid  = threadIdx.x;
    const int warp = tid >> 5;
    const int lane = tid & 31;
    const int gid  = lane >> 2;         // 0..7
    const int tig  = lane & 3;          // 0..3
    const size_t base = (size_t)blockIdx.x * 8192;

    // --- async prefetch q,k (fp16) -> smem; overlaps LN + sym ---
    {
        const uint32_t sqb = smem_u32(sQh);
        const uint32_t skb = smem_u32(sKh);
        const __half* qg = g_q + base;
        const __half* kg = g_k + base;
        #pragma unroll
        for (int r = 0; r < 4; ++r) {
            int f = tid + 256 * r;               // 16B-chunk index 0..1023
            int row = f >> 6, c8 = f & 63;       // 64 chunks of 8 halves per row
            uint32_t off = (uint32_t)(row * PADH + c8 * 8) * 2u;
            asm volatile("cp.async.ca.shared.global [%0], [%1], 16;"
                         :: "r"(sqb + off), "l"(qg + (size_t)row * 512 + c8 * 8));
            asm volatile("cp.async.ca.shared.global [%0], [%1], 16;"
                         :: "r"(skb + off), "l"(kg + (size_t)row * 512 + c8 * 8));
        }
        asm volatile("cp.async.commit_group;" ::: "memory");
    }

    // --- layernorm(mask) -> sM (tf32-rounded): warp per row, 2 rows/warp ---
    #pragma unroll
    for (int p = 0; p < 2; ++p) {
        const int r = warp + p * 8;
        const float4* mg = (const float4*)(mask + base + (size_t)r * 512);
        float4 vv[4];
        float s = 0.f, sq = 0.f;
        #pragma unroll
        for (int u = 0; u < 4; ++u) {
            vv[u] = mg[lane + 32 * u];
            s  += vv[u].x + vv[u].y + vv[u].z + vv[u].w;
            sq += vv[u].x * vv[u].x + vv[u].y * vv[u].y + vv[u].z * vv[u].z + vv[u].w * vv[u].w;
        }
        #pragma unroll
        for (int o = 16; o; o >>= 1) {
            s  += __shfl_xor_sync(0xffffffffu, s,  o);
            sq += __shfl_xor_sync(0xffffffffu, sq, o);
        }
        const float mu  = s * (1.f / 512.f);
        const float inv = rsqrtf(sq * (1.f / 512.f) - mu * mu + 1e-5f);
        float4* mr = (float4*)(sM + r * PADC);
        const float4* gg = (const float4*)ln_g;
        const float4* bv = (const float4*)ln_b;
        #pragma unroll
        for (int u = 0; u < 4; ++u) {
            float4 g4 = gg[lane + 32 * u], b4 = bv[lane + 32 * u];
            mr[lane + 32 * u] = make_float4(f2tf32((vv[u].x - mu) * inv * g4.x + b4.x),
                                            f2tf32((vv[u].y - mu) * inv * g4.y + b4.y),
                                            f2tf32((vv[u].z - mu) * inv * g4.z + b4.z),
                                            f2tf32((vv[u].w - mu) * inv * g4.w + b4.w));
        }
    }
    __syncthreads();

    // --- sym = (m m^T)/sqrt(C) via tf32 mma: warps 0,1 (n-halves) ---
    if (warp < 2) {
        float acc4[4] = {0.f, 0.f, 0.f, 0.f};
        const int nb = warp * 8;
        #pragma unroll 4
        for (int k8 = 0; k8 < 64; ++k8) {
            const int kb = k8 * 8 + tig;
            uint32_t aF[4], bF[2];
            aF[0] = __float_as_uint(sM[gid * PADC + kb]);
            aF[1] = __float_as_uint(sM[(gid + 8) * PADC + kb]);
            aF[2] = __float_as_uint(sM[gid * PADC + kb + 4]);
            aF[3] = __float_as_uint(sM[(gid + 8) * PADC + kb + 4]);
            bF[0] = __float_as_uint(sM[(nb + gid) * PADC + kb]);
            bF[1] = __float_as_uint(sM[(nb + gid) * PADC + kb + 4]);
            mma_tf32(acc4, aF, bF);
        }
        const float S = 0.044194173824159216f;  // 1/sqrt(512)
        const int cc = nb + tig * 2;
        sSym[gid * 16 + cc]           = (gid == cc)         ? 0.f : acc4[0] * S;
        sSym[gid * 16 + cc + 1]       = (gid == cc + 1)     ? 0.f : acc4[1] * S;
        sSym[(gid + 8) * 16 + cc]     = (gid + 8 == cc)     ? 0.f : acc4[2] * S;
        sSym[(gid + 8) * 16 + cc + 1] = (gid + 8 == cc + 1) ? 0.f : acc4[3] * S;
    }
    asm volatile("cp.async.wait_group 0;" ::: "memory");
    __syncthreads();

    // --- sim[h] = q_h k_h^T /8 + sym*beta[h] via fp16 mma: warp h ---
    {
        const int hb = warp * 64;                // head offset (halves)
        const float bh = beta[warp];
        float acc8[2][4];
        #pragma unroll
        for (int nt = 0; nt < 2; ++nt)
            #pragma unroll
            for (int r = 0; r < 4; ++r) acc8[nt][r] = 0.f;

        #pragma unroll
        for (int k16 = 0; k16 < 4; ++k16) {
            const int kb = hb + k16 * 16 + tig * 2;
            uint32_t aF[4], bF[2];
            aF[0] = *(const uint32_t*)(sQh + gid * PADH + kb);
            aF[1] = *(const uint32_t*)(sQh + (gid + 8) * PADH + kb);
            aF[2] = *(const uint32_t*)(sQh + gid * PADH + kb + 8);
            aF[3] = *(const uint32_t*)(sQh + (gid + 8) * PADH + kb + 8);
            #pragma unroll
            for (int nt = 0; nt < 2; ++nt) {
                bF[0] = *(const uint32_t*)(sKh + (nt * 8 + gid) * PADH + kb);
                bF[1] = *(const uint32_t*)(sKh + (nt * 8 + gid) * PADH + kb + 8);
                mma_f16(acc8[nt], aF, bF);
            }
        }
        float* simh = sSim + warp * 256;
        #pragma unroll
        for (int nt = 0; nt < 2; ++nt) {
            const int c0 = nt * 8 + tig * 2;
            simh[gid * 16 + c0]           = acc8[nt][0] * 0.125f + sSym[gid * 16 + c0] * bh;
            simh[gid * 16 + c0 + 1]       = acc8[nt][1] * 0.125f + sSym[gid * 16 + c0 + 1] * bh;
            simh[(gid + 8) * 16 + c0]     = acc8[nt][2] * 0.125f + sSym[(gid + 8) * 16 + c0] * bh;
            simh[(gid + 8) * 16 + c0 + 1] = acc8[nt][3] * 0.125f + sSym[(gid + 8) * 16 + c0 + 1] * bh;
        }
    }
    __syncthreads();

    // --- softmax over j: one thread per (h,i) row ---
    if (tid < 128) {
        float* row = sSim + tid * 16;
        float mx = row[0];
        #pragma unroll
        for (int j = 1; j < 16; ++j) mx = fmaxf(mx, row[j]);
        float s = 0.f;
        #pragma unroll
        for (int j = 0; j < 16; ++j) { float e = __expf(row[j] - mx); row[j] = e; s += e; }
        const float inv = 1.f / s;
        #pragma unroll
        for (int j = 0; j < 16; ++j) row[j] *= inv;
    }
    __syncthreads();

    // --- ctx = attn @ v : thread owns 2 adjacent cols (half2 store);
    //     v[0..15][2 cols] in fp32 regs; h = warp (uniform) ---
    {
        const float2* vg2 = (const float2*)(g_v + base);
        float2 vr[16];
        #pragma unroll
        for (int j = 0; j < 16; ++j) vr[j] = vg2[j * 256 + tid];
        const float* ab = sSim + warp * 256;       // head = warp
        __half2* cg2 = (__half2*)(g_ctx + base);
        #pragma unroll
        for (int i = 0; i < 16; ++i) {
            const float* ar = ab + i * 16;         // broadcast LDS
            float a0 = 0.f, a1 = 0.f;
            #pragma unroll
            for (int j = 0; j < 16; ++j) {
                const float a = ar[j];
                a0 += a * vr[j].x;
                a1 += a * vr[j].y;
            }
            cg2[i * 256 + tid] = __floats2half2_rn(a0, a1);
        }
    }
}

// ---------------------------------------------------------------------------
// Launch
// ---------------------------------------------------------------------------
extern "C" void kernel_launch(void* const* d_in, const int* in_sizes, int n_in,
                              void* d_out, int out_size) {
    const float* x    = (const float*)d_in[0];
    const float* mask = (const float*)d_in[1];
    const float* w_q  = (const float*)d_in[2];
    const float* w_k  = (const float*)d_in[3];
    const float* w_v  = (const float*)d_in[4];
    const float* w_o  = (const float*)d_in[5];
    const float* b_o  = (const float*)d_in[6];
    const float* beta = (const float*)d_in[7];
    const float* ln_g = (const float*)d_in[8];
    const float* ln_b = (const float*)d_in[9];
    float* out = (float*)d_out;

    __half *q, *k, *ctx;
    float  *v;
    cudaGetSymbolAddress((void**)&q,   g_q);
    cudaGetSymbolAddress((void**)&k,   g_k);
    cudaGetSymbolAddress((void**)&v,   g_v);
    cudaGetSymbolAddress((void**)&ctx, g_ctx);

    const int bt = in_sizes[0] / C_DIM;       // B*T = 131072
    const int bb = bt / 16;                   // B   = 8192

    const int gemm_smem = 2 * 2 * 128 * 40 * 2;   // 40960
    const int attn_smem = 75520;
    cudaFuncSetAttribute((const void*)gemm_kernel<false, true>,
                         cudaFuncAttributeMaxDynamicSharedMemorySize, gemm_smem);
    cudaFuncSetAttribute((const void*)gemm_kernel<false, false>,
                         cudaFuncAttributeMaxDynamicSharedMemorySize, gemm_smem);
    cudaFuncSetAttribute((const void*)gemm_kernel<true, false>,
                         cudaFuncAttributeMaxDynamicSharedMemorySize, gemm_smem);
    cudaFuncSetAttribute((const void*)attn_kernel,
                         cudaFuncAttributeMaxDynamicSharedMemorySize, attn_smem);

    dim3 grid(4, bt / 128);                   // N/128 x M/128
    gemm_kernel<false, true ><<<grid, 256, gemm_smem>>>(x,   w_q, q,   nullptr);
    gemm_kernel<false, true ><<<grid, 256, gemm_smem>>>(x,   w_k, k,   nullptr);
    gemm_kernel<false, false><<<grid, 256, gemm_smem>>>(x,   w_v, v,   nullptr);
    attn_kernel<<<bb, 256, attn_smem>>>(mask, ln_g, ln_b, beta);
    gemm_kernel<true,  false><<<grid, 256, gemm_smem>>>(ctx, w_o, out, b_o);
}

// round 10
// speedup vs baseline: 2.2558x; 1.0461x over previous
#include <cuda_runtime.h>
#include <cuda_fp16.h>
#include <cstdint>
#include <cstddef>

// Problem shape (fixed by the dataset): B=8192, T=16, C=512, H=8, DH=64
#define BT_TOTAL 131072          // B*T
#define B_TOTAL  8192
#define C_DIM    512

// ---------------------------------------------------------------------------
// Scratch (device globals; no allocations allowed). All fp16: each consumer
// applies (or tolerates) 10-bit-mantissa rounding anyway.
// ---------------------------------------------------------------------------
__device__ __half g_q[BT_TOTAL * C_DIM];     // 128 MiB each
__device__ __half g_k[BT_TOTAL * C_DIM];
__device__ __half g_v[BT_TOTAL * C_DIM];
__device__ __half g_ctx[BT_TOTAL * C_DIM];

// ---------------------------------------------------------------------------
// Helpers
// ---------------------------------------------------------------------------
__device__ __forceinline__ uint32_t smem_u32(const void* p) {
    uint32_t a;
    asm("{ .reg .u64 t; cvta.to.shared.u64 t, %1; cvt.u32.u64 %0, t; }" : "=r"(a) : "l"(p));
    return a;
}
__device__ __forceinline__ uint32_t h2b(__half2 h) {
    return *reinterpret_cast<uint32_t*>(&h);
}
__device__ __forceinline__ void mma_f16(float* d, const uint32_t* a, const uint32_t* b) {
    asm volatile(
        "mma.sync.aligned.m16n8k16.row.col.f32.f16.f16.f32 "
        "{%0,%1,%2,%3}, {%4,%5,%6,%7}, {%8,%9}, {%0,%1,%2,%3};\n"
        : "+f"(d[0]), "+f"(d[1]), "+f"(d[2]), "+f"(d[3])
        : "r"(a[0]), "r"(a[1]), "r"(a[2]), "r"(a[3]),
          "r"(b[0]), "r"(b[1]));
}

// ===========================================================================
// GEMM mainloop macros (shared between the two GEMM kernels)
// Tile 128x128x32, 256 threads, fp16 mma m16n8k16, double-buffered smem.
// ===========================================================================
#define GEMM_DECLS                                                             \
    constexpr int K = 512;                                                     \
    constexpr int N = 512;                                                     \
    constexpr int LDSH = 40;                                                   \
    constexpr int BUFH = 128 * LDSH;                                           \
    extern __shared__ __half hsm[];                                            \
    __half* As = hsm;                                                          \
    __half* Bs = hsm + 2 * BUFH;                                               \
    const int tid   = threadIdx.x;                                             \
    const int lane  = tid & 31;                                                \
    const int warp  = tid >> 5;                                                \
    const int warpM = warp >> 2;                                               \
    const int warpN = warp & 3;                                                \
    const int gid   = lane >> 2;                                               \
    const int tig   = lane & 3;                                                \
    const int lrow = tid >> 3;                                                 \
    const int lcol = (tid & 7) << 2;                                           \
    float acc[4][4][4];                                                        \
    _Pragma("unroll")                                                          \
    for (int i = 0; i < 4; ++i)                                                \
        _Pragma("unroll")                                                      \
        for (int j = 0; j < 4; ++j)                                            \
            _Pragma("unroll")                                                  \
            for (int r = 0; r < 4; ++r) acc[i][j][r] = 0.f;

#define GEMM_MAINLOOP(G2R_BODY, R2S_BODY)                                      \
    { G2R_BODY(0) }                                                            \
    { R2S_BODY(0) }                                                            \
    __syncthreads();                                                           \
    _Pragma("unroll 1")                                                        \
    for (int kt = 0; kt < 16; ++kt) {                                          \
        const int cur = kt & 1;                                                \
        if (kt + 1 < 16) { G2R_BODY(kt + 1) }                                  \
        const __half* as = As + cur * BUFH;                                    \
        const __half* bs = Bs + cur * BUFH;                                    \
        _Pragma("unroll")                                                      \
        for (int ks = 0; ks < 2; ++ks) {                                       \
            const int kb = ks * 16 + tig * 2;                                  \
            uint32_t aF[4][4];                                                 \
            uint32_t bF[4][2];                                                 \
            _Pragma("unroll")                                                  \
            for (int mt = 0; mt < 4; ++mt) {                                   \
                const int rb = warpM * 64 + mt * 16;                           \
                aF[mt][0] = *(const uint32_t*)(as + (rb + gid)     * LDSH + kb);     \
                aF[mt][1] = *(const uint32_t*)(as + (rb + gid + 8) * LDSH + kb);     \
                aF[mt][2] = *(const uint32_t*)(as + (rb + gid)     * LDSH + kb + 8); \
                aF[mt][3] = *(const uint32_t*)(as + (rb + gid + 8) * LDSH + kb + 8); \
            }                                                                  \
            _Pragma("unroll")                                                  \
            for (int nt = 0; nt < 4; ++nt) {                                   \
                const int cb = warpN * 32 + nt * 8;                            \
                bF[nt][0] = *(const uint32_t*)(bs + (cb + gid) * LDSH + kb);       \
                bF[nt][1] = *(const uint32_t*)(bs + (cb + gid) * LDSH + kb + 8);   \
            }                                                                  \
            _Pragma("unroll")                                                  \
            for (int mt = 0; mt < 4; ++mt)                                     \
                _Pragma("unroll")                                              \
                for (int nt = 0; nt < 4; ++nt)                                 \
                    mma_f16(acc[mt][nt], aF[mt], bF[nt]);                      \
        }                                                                      \
        if (kt + 1 < 16) { R2S_BODY((kt + 1) & 1) }                            \
        __syncthreads();                                                       \
    }

// ---------------------------------------------------------------------------
// Merged QKV GEMM: grid (12, M/128). blockIdx.x>>2 selects {q,k,v};
// blockIdx.x&3 is the N-tile. A = x (fp32, converted on stage), out fp16.
// Consecutive CTAs share the same A block -> L2 reuse; single launch kills
// two of the three wave tails.
// ---------------------------------------------------------------------------
__global__ __launch_bounds__(256, 2)
void gemm_qkv_kernel(const float* __restrict__ A,
                     const float* __restrict__ Wq, const float* __restrict__ Wk,
                     const float* __restrict__ Wv,
                     __half* __restrict__ Oq, __half* __restrict__ Ok,
                     __half* __restrict__ Ov) {
    GEMM_DECLS
    const int sel = blockIdx.x >> 2;
    const int bn  = blockIdx.x & 3;
    const int bm  = blockIdx.y;

    const float* Bw = (sel == 0) ? Wq : (sel == 1) ? Wk : Wv;
    __half*      Co = (sel == 0) ? Oq : (sel == 1) ? Ok : Ov;

    const float* Ag = A  + (size_t)bm * 128 * K;
    const float* Bg = Bw + (size_t)bn * 128 * K;

    float4 aR[4], bR[4];

    #define QKV_G2R(kt)                                                        \
        {                                                                      \
            const float* ap = Ag + (size_t)lrow * K + (kt) * 32 + lcol;        \
            const float* bp = Bg + (size_t)lrow * K + (kt) * 32 + lcol;        \
            _Pragma("unroll")                                                  \
            for (int r = 0; r < 4; ++r) {                                      \
                aR[r] = *(const float4*)(ap + (size_t)r * 32 * K);             \
                bR[r] = *(const float4*)(bp + (size_t)r * 32 * K);             \
            }                                                                  \
        }
    #define QKV_R2S(buf)                                                       \
        {                                                                      \
            __half* as = As + (buf) * BUFH;                                    \
            __half* bs = Bs + (buf) * BUFH;                                    \
            _Pragma("unroll")                                                  \
            for (int r = 0; r < 4; ++r) {                                      \
                int row = lrow + r * 32;                                       \
                uint2 ua = make_uint2(h2b(__floats2half2_rn(aR[r].x, aR[r].y)),\
                                      h2b(__floats2half2_rn(aR[r].z, aR[r].w)));\
                uint2 ub = make_uint2(h2b(__floats2half2_rn(bR[r].x, bR[r].y)),\
                                      h2b(__floats2half2_rn(bR[r].z, bR[r].w)));\
                *(uint2*)(as + row * LDSH + lcol) = ua;                        \
                *(uint2*)(bs + row * LDSH + lcol) = ub;                        \
            }                                                                  \
        }

    GEMM_MAINLOOP(QKV_G2R, QKV_R2S)
    #undef QKV_G2R
    #undef QKV_R2S

    const size_t cbase = (size_t)bm * 128 * N + (size_t)bn * 128;
    #pragma unroll
    for (int mt = 0; mt < 4; ++mt) {
        const int r0 = warpM * 64 + mt * 16 + gid;
        #pragma unroll
        for (int nt = 0; nt < 4; ++nt) {
            const int c0 = warpN * 32 + nt * 8 + tig * 2;
            size_t o = cbase + (size_t)r0 * N + c0;
            *(__half2*)(Co + o)         = __floats2half2_rn(acc[mt][nt][0], acc[mt][nt][1]);
            *(__half2*)(Co + o + 8 * N) = __floats2half2_rn(acc[mt][nt][2], acc[mt][nt][3]);
        }
    }
}

// ---------------------------------------------------------------------------
// Output GEMM: A = ctx (fp16 in gmem, raw loads), C = out (fp32 + bias).
// ---------------------------------------------------------------------------
__global__ __launch_bounds__(256, 2)
void gemm_out_kernel(const __half* __restrict__ A, const float* __restrict__ Bw,
                     float* __restrict__ Cout, const float* __restrict__ bias) {
    GEMM_DECLS
    const int bn = blockIdx.x;
    const int bm = blockIdx.y;

    const __half* Ag = A  + (size_t)bm * 128 * K;
    const float*  Bg = Bw + (size_t)bn * 128 * K;

    uint2  aRh[4];
    float4 bR[4];

    #define OUT_G2R(kt)                                                        \
        {                                                                      \
            const __half* ap = Ag + (size_t)lrow * K + (kt) * 32 + lcol;       \
            const float*  bp = Bg + (size_t)lrow * K + (kt) * 32 + lcol;       \
            _Pragma("unroll")                                                  \
            for (int r = 0; r < 4; ++r) {                                      \
                aRh[r] = *(const uint2*)(ap + (size_t)r * 32 * K);             \
                bR[r]  = *(const float4*)(bp + (size_t)r * 32 * K);            \
            }                                                                  \
        }
    #define OUT_R2S(buf)                                                       \
        {                                                                      \
            __half* as = As + (buf) * BUFH;                                    \
            __half* bs = Bs + (buf) * BUFH;                                    \
            _Pragma("unroll")                                                  \
            for (int r = 0; r < 4; ++r) {                                      \
                int row = lrow + r * 32;                                       \
                *(uint2*)(as + row * LDSH + lcol) = aRh[r];                    \
                uint2 ub = make_uint2(h2b(__floats2half2_rn(bR[r].x, bR[r].y)),\
                                      h2b(__floats2half2_rn(bR[r].z, bR[r].w)));\
                *(uint2*)(bs + row * LDSH + lcol) = ub;                        \
            }                                                                  \
        }

    GEMM_MAINLOOP(OUT_G2R, OUT_R2S)
    #undef OUT_G2R
    #undef OUT_R2S

    const size_t cbase = (size_t)bm * 128 * N + (size_t)bn * 128;
    #pragma unroll
    for (int mt = 0; mt < 4; ++mt) {
        const int r0 = warpM * 64 + mt * 16 + gid;
        #pragma unroll
        for (int nt = 0; nt < 4; ++nt) {
            const int c0 = warpN * 32 + nt * 8 + tig * 2;
            const float b0 = bias[bn * 128 + c0];
            const float b1 = bias[bn * 128 + c0 + 1];
            size_t o = cbase + (size_t)r0 * N + c0;
            *(float2*)(Cout + o)         = make_float2(acc[mt][nt][0] + b0, acc[mt][nt][1] + b1);
            *(float2*)(Cout + o + 8 * N) = make_float2(acc[mt][nt][2] + b0, acc[mt][nt][3] + b1);
        }
    }
}

// ---------------------------------------------------------------------------
// Fused attention middle: CTA per batch.
//   m = LN(mask[b]) -> fp16; sym = (m m^T)/sqrt(C) via fp16 mma, zero diag
//   sim[h,i,j] = (q_i.k_j)/8 + sym*beta[h] via fp16 mma; softmax (fp32)
//   ctx = attn @ v (v fp16 -> exact fp32 FMA), stored fp16
// ---------------------------------------------------------------------------
__global__ __launch_bounds__(256, 3)
void attn_kernel(const float* __restrict__ mask,
                 const float* __restrict__ ln_g, const float* __restrict__ ln_b,
                 const float* __restrict__ beta) {
    constexpr int PADH = 520;   // fp16 row stride (halves)
    extern __shared__ char smraw[];
    float*  sSym = (float*)(smraw);                  // 256 f   @ 0     (1024B)
    float*  sSim = (float*)(smraw + 1024);           // 2048 f  @ 1024  (8192B)
    __half* sQh  = (__half*)(smraw + 9216);          // 16*520 h (16640B)
    __half* sKh  = (__half*)(smraw + 25856);         // 16*520 h
    __half* sMh  = (__half*)(smraw + 42496);         // 16*520 h  (end 59136)

    const int tid  = threadIdx.x;
    const int warp = tid >> 5;
    const int lane = tid & 31;
    const int gid  = lane >> 2;         // 0..7
    const int tig  = lane & 3;          // 0..3
    const size_t base = (size_t)blockIdx.x * 8192;

    // --- async prefetch q,k (fp16) -> smem; overlaps LN + sym ---
    {
        const uint32_t sqb = smem_u32(sQh);
        const uint32_t skb = smem_u32(sKh);
        const __half* qg = g_q + base;
        const __half* kg = g_k + base;
        #pragma unroll
        for (int r = 0; r < 4; ++r) {
            int f = tid + 256 * r;               // 16B-chunk index 0..1023
            int row = f >> 6, c8 = f & 63;
            uint32_t off = (uint32_t)(row * PADH + c8 * 8) * 2u;
            asm volatile("cp.async.ca.shared.global [%0], [%1], 16;"
                         :: "r"(sqb + off), "l"(qg + (size_t)row * 512 + c8 * 8));
            asm volatile("cp.async.ca.shared.global [%0], [%1], 16;"
                         :: "r"(skb + off), "l"(kg + (size_t)row * 512 + c8 * 8));
        }
        asm volatile("cp.async.commit_group;" ::: "memory");
    }

    // --- layernorm(mask) -> sMh (fp16): warp per row, 2 rows/warp ---
    #pragma unroll
    for (int p = 0; p < 2; ++p) {
        const int r = warp + p * 8;
        const float4* mg = (const float4*)(mask + base + (size_t)r * 512);
        float4 vv[4];
        float s = 0.f, sq = 0.f;
        #pragma unroll
        for (int u = 0; u < 4; ++u) {
            vv[u] = mg[lane + 32 * u];
            s  += vv[u].x + vv[u].y + vv[u].z + vv[u].w;
            sq += vv[u].x * vv[u].x + vv[u].y * vv[u].y + vv[u].z * vv[u].z + vv[u].w * vv[u].w;
        }
        #pragma unroll
        for (int o = 16; o; o >>= 1) {
            s  += __shfl_xor_sync(0xffffffffu, s,  o);
            sq += __shfl_xor_sync(0xffffffffu, sq, o);
        }
        const float mu  = s * (1.f / 512.f);
        const float inv = rsqrtf(sq * (1.f / 512.f) - mu * mu + 1e-5f);
        const float4* gg = (const float4*)ln_g;
        const float4* bv = (const float4*)ln_b;
        uint2* mr = (uint2*)(sMh + r * PADH);        // 4 halves per uint2
        #pragma unroll
        for (int u = 0; u < 4; ++u) {
            float4 g4 = gg[lane + 32 * u], b4 = bv[lane + 32 * u];
            float m0 = (vv[u].x - mu) * inv * g4.x + b4.x;
            float m1 = (vv[u].y - mu) * inv * g4.y + b4.y;
            float m2 = (vv[u].z - mu) * inv * g4.z + b4.z;
            float m3 = (vv[u].w - mu) * inv * g4.w + b4.w;
            mr[lane + 32 * u] = make_uint2(h2b(__floats2half2_rn(m0, m1)),
                                           h2b(__floats2half2_rn(m2, m3)));
        }
    }
    __syncthreads();

    // --- sym = (m m^T)/sqrt(C) via fp16 mma: warps 0,1 (n-halves) ---
    if (warp < 2) {
        float acc4[4] = {0.f, 0.f, 0.f, 0.f};
        const int nb = warp * 8;
        #pragma unroll 4
        for (int k16 = 0; k16 < 32; ++k16) {
            const int kb = k16 * 16 + tig * 2;
            uint32_t aF[4], bF[2];
            aF[0] = *(const uint32_t*)(sMh + gid * PADH + kb);
            aF[1] = *(const uint32_t*)(sMh + (gid + 8) * PADH + kb);
            aF[2] = *(const uint32_t*)(sMh + gid * PADH + kb + 8);
            aF[3] = *(const uint32_t*)(sMh + (gid + 8) * PADH + kb + 8);
            bF[0] = *(const uint32_t*)(sMh + (nb + gid) * PADH + kb);
            bF[1] = *(const uint32_t*)(sMh + (nb + gid) * PADH + kb + 8);
            mma_f16(acc4, aF, bF);
        }
        const float S = 0.044194173824159216f;  // 1/sqrt(512)
        const int cc = nb + tig * 2;
        sSym[gid * 16 + cc]           = (gid == cc)         ? 0.f : acc4[0] * S;
        sSym[gid * 16 + cc + 1]       = (gid == cc + 1)     ? 0.f : acc4[1] * S;
        sSym[(gid + 8) * 16 + cc]     = (gid + 8 == cc)     ? 0.f : acc4[2] * S;
        sSym[(gid + 8) * 16 + cc + 1] = (gid + 8 == cc + 1) ? 0.f : acc4[3] * S;
    }
    asm volatile("cp.async.wait_group 0;" ::: "memory");
    __syncthreads();

    // --- sim[h] = q_h k_h^T /8 + sym*beta[h] via fp16 mma: warp h ---
    {
        const int hb = warp * 64;                // head offset (halves)
        const float bh = beta[warp];
        float acc8[2][4];
        #pragma unroll
        for (int nt = 0; nt < 2; ++nt)
            #pragma unroll
            for (int r = 0; r < 4; ++r) acc8[nt][r] = 0.f;

        #pragma unroll
        for (int k16 = 0; k16 < 4; ++k16) {
            const int kb = hb + k16 * 16 + tig * 2;
            uint32_t aF[4], bF[2];
            aF[0] = *(const uint32_t*)(sQh + gid * PADH + kb);
            aF[1] = *(const uint32_t*)(sQh + (gid + 8) * PADH + kb);
            aF[2] = *(const uint32_t*)(sQh + gid * PADH + kb + 8);
            aF[3] = *(const uint32_t*)(sQh + (gid + 8) * PADH + kb + 8);
            #pragma unroll
            for (int nt = 0; nt < 2; ++nt) {
                bF[0] = *(const uint32_t*)(sKh + (nt * 8 + gid) * PADH + kb);
                bF[1] = *(const uint32_t*)(sKh + (nt * 8 + gid) * PADH + kb + 8);
                mma_f16(acc8[nt], aF, bF);
            }
        }
        float* simh = sSim + warp * 256;
        #pragma unroll
        for (int nt = 0; nt < 2; ++nt) {
            const int c0 = nt * 8 + tig * 2;
            simh[gid * 16 + c0]           = acc8[nt][0] * 0.125f + sSym[gid * 16 + c0] * bh;
            simh[gid * 16 + c0 + 1]       = acc8[nt][1] * 0.125f + sSym[gid * 16 + c0 + 1] * bh;
            simh[(gid + 8) * 16 + c0]     = acc8[nt][2] * 0.125f + sSym[(gid + 8) * 16 + c0] * bh;
            simh[(gid + 8) * 16 + c0 + 1] = acc8[nt][3] * 0.125f + sSym[(gid + 8) * 16 + c0 + 1] * bh;
        }
    }
    __syncthreads();

    // --- softmax over j: one thread per (h,i) row ---
    if (tid < 128) {
        float* row = sSim + tid * 16;
        float mx = row[0];
        #pragma unroll
        for (int j = 1; j < 16; ++j) mx = fmaxf(mx, row[j]);
        float s = 0.f;
        #pragma unroll
        for (int j = 0; j < 16; ++j) { float e = __expf(row[j] - mx); row[j] = e; s += e; }
        const float inv = 1.f / s;
        #pragma unroll
        for (int j = 0; j < 16; ++j) row[j] *= inv;
    }
    __syncthreads();

    // --- ctx = attn @ v : thread owns 2 adjacent cols (half2 loads/stores);
    //     v[0..15] converted to fp32 regs; h = warp (uniform) ---
    {
        const __half2* vg2 = (const __half2*)(g_v + base);
        float2 vr[16];
        #pragma unroll
        for (int j = 0; j < 16; ++j) vr[j] = __half22float2(vg2[j * 256 + tid]);
        const float* ab = sSim + warp * 256;       // head = warp
        __half2* cg2 = (__half2*)(g_ctx + base);
        #pragma unroll
        for (int i = 0; i < 16; ++i) {
            const float* ar = ab + i * 16;         // broadcast LDS
            float a0 = 0.f, a1 = 0.f;
            #pragma unroll
            for (int j = 0; j < 16; ++j) {
                const float a = ar[j];
                a0 += a * vr[j].x;
                a1 += a * vr[j].y;
            }
            cg2[i * 256 + tid] = __floats2half2_rn(a0, a1);
        }
    }
}

// ---------------------------------------------------------------------------
// Launch
// ---------------------------------------------------------------------------
extern "C" void kernel_launch(void* const* d_in, const int* in_sizes, int n_in,
                              void* d_out, int out_size) {
    const float* x    = (const float*)d_in[0];
    const float* mask = (const float*)d_in[1];
    const float* w_q  = (const float*)d_in[2];
    const float* w_k  = (const float*)d_in[3];
    const float* w_v  = (const float*)d_in[4];
    const float* w_o  = (const float*)d_in[5];
    const float* b_o  = (const float*)d_in[6];
    const float* beta = (const float*)d_in[7];
    const float* ln_g = (const float*)d_in[8];
    const float* ln_b = (const float*)d_in[9];
    float* out = (float*)d_out;

    __half *q, *k, *v, *ctx;
    cudaGetSymbolAddress((void**)&q,   g_q);
    cudaGetSymbolAddress((void**)&k,   g_k);
    cudaGetSymbolAddress((void**)&v,   g_v);
    cudaGetSymbolAddress((void**)&ctx, g_ctx);

    const int bt = in_sizes[0] / C_DIM;       // B*T = 131072
    const int bb = bt / 16;                   // B   = 8192

    const int gemm_smem = 2 * 2 * 128 * 40 * 2;   // 40960
    const int attn_smem = 59136;
    cudaFuncSetAttribute(gemm_qkv_kernel, cudaFuncAttributeMaxDynamicSharedMemorySize, gemm_smem);
    cudaFuncSetAttribute(gemm_out_kernel, cudaFuncAttributeMaxDynamicSharedMemorySize, gemm_smem);
    cudaFuncSetAttribute(attn_kernel,     cudaFuncAttributeMaxDynamicSharedMemorySize, attn_smem);

    dim3 grid_qkv(12, bt / 128);              // 3 outputs x 4 N-tiles
    dim3 grid_out(4,  bt / 128);
    gemm_qkv_kernel<<<grid_qkv, 256, gemm_smem>>>(x, w_q, w_k, w_v, q, k, v);
    attn_kernel<<<bb, 256, attn_smem>>>(mask, ln_g, ln_b, beta);
    gemm_out_kernel<<<grid_out, 256, gemm_smem>>>(ctx, w_o, out, b_o);
}

// round 11
// speedup vs baseline: 2.5184x; 1.1164x over previous
#include <cuda_runtime.h>
#include <cuda_fp16.h>
#include <cstdint>
#include <cstddef>

// Problem shape (fixed by the dataset): B=8192, T=16, C=512, H=8, DH=64
#define BT_TOTAL 131072          // B*T
#define C_DIM    512

// ---------------------------------------------------------------------------
// Scratch (device globals; no allocations allowed). All fp16.
// ---------------------------------------------------------------------------
__device__ __half g_xh[BT_TOTAL * C_DIM];    // x converted to fp16
__device__ __half g_wq[C_DIM * C_DIM];
__device__ __half g_wk[C_DIM * C_DIM];
__device__ __half g_wv[C_DIM * C_DIM];
__device__ __half g_wo[C_DIM * C_DIM];
__device__ __half g_q[BT_TOTAL * C_DIM];
__device__ __half g_k[BT_TOTAL * C_DIM];
__device__ __half g_v[BT_TOTAL * C_DIM];
__device__ __half g_ctx[BT_TOTAL * C_DIM];

// ---------------------------------------------------------------------------
// Helpers
// ---------------------------------------------------------------------------
__device__ __forceinline__ uint32_t smem_u32(const void* p) {
    uint32_t a;
    asm("{ .reg .u64 t; cvta.to.shared.u64 t, %1; cvt.u32.u64 %0, t; }" : "=r"(a) : "l"(p));
    return a;
}
__device__ __forceinline__ uint32_t h2b(__half2 h) {
    return *reinterpret_cast<uint32_t*>(&h);
}
__device__ __forceinline__ void mma_f16(float* d, const uint32_t* a, const uint32_t* b) {
    asm volatile(
        "mma.sync.aligned.m16n8k16.row.col.f32.f16.f16.f32 "
        "{%0,%1,%2,%3}, {%4,%5,%6,%7}, {%8,%9}, {%0,%1,%2,%3};\n"
        : "+f"(d[0]), "+f"(d[1]), "+f"(d[2]), "+f"(d[3])
        : "r"(a[0]), "r"(a[1]), "r"(a[2]), "r"(a[3]),
          "r"(b[0]), "r"(b[1]));
}
#define LDSM4(r0, r1, r2, r3, addr)                                            \
    asm volatile("ldmatrix.sync.aligned.m8n8.x4.shared.b16 {%0,%1,%2,%3}, [%4];" \
        : "=r"(r0), "=r"(r1), "=r"(r2), "=r"(r3) : "r"(addr))
#define CP_ASYNC16(dst, src)                                                   \
    asm volatile("cp.async.cg.shared.global [%0], [%1], 16;" :: "r"(dst), "l"(src))
#define CP_COMMIT()  asm volatile("cp.async.commit_group;" ::: "memory")
#define CP_WAIT(n)   asm volatile("cp.async.wait_group %0;" :: "n"(n) : "memory")

// ---------------------------------------------------------------------------
// fp32 -> fp16 bulk convert (4 floats per thread)
// ---------------------------------------------------------------------------
__global__ __launch_bounds__(256)
void cvt_kernel(const float4* __restrict__ src, uint2* __restrict__ dst, int n4) {
    int i = blockIdx.x * 256 + threadIdx.x;
    if (i < n4) {
        float4 v = src[i];
        dst[i] = make_uint2(h2b(__floats2half2_rn(v.x, v.y)),
                            h2b(__floats2half2_rn(v.z, v.w)));
    }
}

// ===========================================================================
// fp16 GEMM core: C[m,n] = sum_k A[m,k]*B[n,k]. Tile 128x128x32, 256 thr.
// 3-stage cp.async pipeline, ldmatrix fragment loads.
// smem: A stages @ s*10240, B stages @ 30720 + s*10240. Total 61440 B.
// Row stride 40 halves (80 B): LDSM-phase conflict-free (5r mod 8 distinct).
// ===========================================================================
#define GEMM_CORE_DECLS                                                        \
    extern __shared__ char smraw[];                                            \
    const uint32_t sbase = smem_u32(smraw);                                    \
    const int tid   = threadIdx.x;                                             \
    const int lane  = tid & 31;                                                \
    const int warp  = tid >> 5;                                                \
    const int warpM = warp >> 2;                                               \
    const int warpN = warp & 3;                                                \
    const int gid   = lane >> 2;                                               \
    const int tig   = lane & 3;                                                \
    const uint32_t aOff = (uint32_t)((warpM * 64 + (lane & 15)) * 80 + (lane >> 4) * 16); \
    const uint32_t bOff = (uint32_t)((warpN * 32 + (lane >> 4) * 8 + (lane & 7)) * 80     \
                                     + ((lane >> 3) & 1) * 16);                \
    float acc[4][4][4];                                                        \
    _Pragma("unroll")                                                          \
    for (int i = 0; i < 4; ++i)                                                \
        _Pragma("unroll")                                                      \
        for (int j = 0; j < 4; ++j)                                            \
            _Pragma("unroll")                                                  \
            for (int r = 0; r < 4; ++r) acc[i][j][r] = 0.f;

#define GEMM_ISSUE(kt)                                                         \
    {                                                                          \
        const int s_ = (kt) % 3;                                               \
        const uint32_t da_ = sbase + s_ * 10240;                               \
        const uint32_t db_ = sbase + 30720 + s_ * 10240;                       \
        const __half* ag_ = Ag + (kt) * 32;                                    \
        const __half* bg_ = Bg + (kt) * 32;                                    \
        _Pragma("unroll")                                                      \
        for (int i_ = 0; i_ < 2; ++i_) {                                       \
            const int idx_ = tid + i_ * 256;                                   \
            const int row_ = idx_ >> 2, c_ = idx_ & 3;                         \
            CP_ASYNC16(da_ + (uint32_t)(row_ * 80 + c_ * 16),                  \
                       ag_ + (size_t)row_ * 512 + c_ * 8);                     \
            CP_ASYNC16(db_ + (uint32_t)(row_ * 80 + c_ * 16),                  \
                       bg_ + (size_t)row_ * 512 + c_ * 8);                     \
        }                                                                      \
        CP_COMMIT();                                                           \
    }

#define GEMM_COMPUTE(s)                                                        \
    {                                                                          \
        const uint32_t sa_ = sbase + (s) * 10240 + aOff;                       \
        const uint32_t sb_ = sbase + 30720 + (s) * 10240 + bOff;               \
        _Pragma("unroll")                                                      \
        for (int ks = 0; ks < 2; ++ks) {                                       \
            uint32_t aF[4][4], bF[8];                                          \
            _Pragma("unroll")                                                  \
            for (int mt = 0; mt < 4; ++mt)                                     \
                LDSM4(aF[mt][0], aF[mt][1], aF[mt][2], aF[mt][3],              \
                      sa_ + mt * 1280 + ks * 32);                              \
            _Pragma("unroll")                                                  \
            for (int p = 0; p < 2; ++p)                                        \
                LDSM4(bF[p*4], bF[p*4+1], bF[p*4+2], bF[p*4+3],                \
                      sb_ + p * 1280 + ks * 32);                               \
            _Pragma("unroll")                                                  \
            for (int mt = 0; mt < 4; ++mt)                                     \
                _Pragma("unroll")                                              \
                for (int nt = 0; nt < 4; ++nt)                                 \
                    mma_f16(acc[mt][nt], aF[mt], &bF[nt * 2]);                 \
        }                                                                      \
    }

#define GEMM_MAINLOOP                                                          \
    GEMM_ISSUE(0)                                                              \
    GEMM_ISSUE(1)                                                              \
    _Pragma("unroll 1")                                                        \
    for (int kt = 0; kt < 16; ++kt) {                                          \
        if (kt + 2 < 16) { GEMM_ISSUE(kt + 2) } else { CP_COMMIT(); }          \
        CP_WAIT(2);                                                            \
        __syncthreads();                                                       \
        GEMM_COMPUTE(kt % 3)                                                   \
        __syncthreads();                                                       \
    }

// ---------------------------------------------------------------------------
// Merged QKV GEMM: grid (12, M/128). blockIdx.x>>2 selects {q,k,v}.
// A = g_xh fp16, B = pre-converted weights fp16, out fp16.
// ---------------------------------------------------------------------------
__global__ __launch_bounds__(256, 2)
void gemm_qkv_kernel(const __half* __restrict__ A,
                     __half* __restrict__ Oq, __half* __restrict__ Ok,
                     __half* __restrict__ Ov) {
    GEMM_CORE_DECLS
    const int sel = blockIdx.x >> 2;
    const int bn  = blockIdx.x & 3;
    const int bm  = blockIdx.y;

    const __half* Bw = (sel == 0) ? g_wq : (sel == 1) ? g_wk : g_wv;
    __half*       Co = (sel == 0) ? Oq   : (sel == 1) ? Ok   : Ov;

    const __half* Ag = A  + (size_t)bm * 128 * 512;
    const __half* Bg = Bw + (size_t)bn * 128 * 512;

    GEMM_MAINLOOP

    const size_t cbase = (size_t)bm * 128 * 512 + (size_t)bn * 128;
    #pragma unroll
    for (int mt = 0; mt < 4; ++mt) {
        const int r0 = warpM * 64 + mt * 16 + gid;
        #pragma unroll
        for (int nt = 0; nt < 4; ++nt) {
            const int c0 = warpN * 32 + nt * 8 + tig * 2;
            size_t o = cbase + (size_t)r0 * 512 + c0;
            *(__half2*)(Co + o)           = __floats2half2_rn(acc[mt][nt][0], acc[mt][nt][1]);
            *(__half2*)(Co + o + 8 * 512) = __floats2half2_rn(acc[mt][nt][2], acc[mt][nt][3]);
        }
    }
}

// ---------------------------------------------------------------------------
// Output GEMM: A = g_ctx fp16, B = g_wo fp16, C = out fp32 + bias.
// ---------------------------------------------------------------------------
__global__ __launch_bounds__(256, 2)
void gemm_out_kernel(const __half* __restrict__ A, float* __restrict__ Cout,
                     const float* __restrict__ bias) {
    GEMM_CORE_DECLS
    const int bn = blockIdx.x;
    const int bm = blockIdx.y;

    const __half* Ag = A    + (size_t)bm * 128 * 512;
    const __half* Bg = g_wo + (size_t)bn * 128 * 512;

    GEMM_MAINLOOP

    const size_t cbase = (size_t)bm * 128 * 512 + (size_t)bn * 128;
    #pragma unroll
    for (int mt = 0; mt < 4; ++mt) {
        const int r0 = warpM * 64 + mt * 16 + gid;
        #pragma unroll
        for (int nt = 0; nt < 4; ++nt) {
            const int c0 = warpN * 32 + nt * 8 + tig * 2;
            const float b0 = bias[bn * 128 + c0];
            const float b1 = bias[bn * 128 + c0 + 1];
            size_t o = cbase + (size_t)r0 * 512 + c0;
            *(float2*)(Cout + o)           = make_float2(acc[mt][nt][0] + b0, acc[mt][nt][1] + b1);
            *(float2*)(Cout + o + 8 * 512) = make_float2(acc[mt][nt][2] + b0, acc[mt][nt][3] + b1);
        }
    }
}

// ---------------------------------------------------------------------------
// Fused attention middle (unchanged from R10): CTA per batch.
// ---------------------------------------------------------------------------
__global__ __launch_bounds__(256, 3)
void attn_kernel(const float* __restrict__ mask,
                 const float* __restrict__ ln_g, const float* __restrict__ ln_b,
                 const float* __restrict__ beta) {
    constexpr int PADH = 520;   // fp16 row stride (halves)
    extern __shared__ char smraw[];
    float*  sSym = (float*)(smraw);                  // 256 f
    float*  sSim = (float*)(smraw + 1024);           // 2048 f
    __half* sQh  = (__half*)(smraw + 9216);          // 16*520 h
    __half* sKh  = (__half*)(smraw + 25856);         // 16*520 h
    __half* sMh  = (__half*)(smraw + 42496);         // 16*520 h (end 59136)

    const int tid  = threadIdx.x;
    const int warp = tid >> 5;
    const int lane = tid & 31;
    const int gid  = lane >> 2;
    const int tig  = lane & 3;
    const size_t base = (size_t)blockIdx.x * 8192;

    // async prefetch q,k (fp16) -> smem; overlaps LN + sym
    {
        const uint32_t sqb = smem_u32(sQh);
        const uint32_t skb = smem_u32(sKh);
        const __half* qg = g_q + base;
        const __half* kg = g_k + base;
        #pragma unroll
        for (int r = 0; r < 4; ++r) {
            int f = tid + 256 * r;
            int row = f >> 6, c8 = f & 63;
            uint32_t off = (uint32_t)(row * PADH + c8 * 8) * 2u;
            asm volatile("cp.async.ca.shared.global [%0], [%1], 16;"
                         :: "r"(sqb + off), "l"(qg + (size_t)row * 512 + c8 * 8));
            asm volatile("cp.async.ca.shared.global [%0], [%1], 16;"
                         :: "r"(skb + off), "l"(kg + (size_t)row * 512 + c8 * 8));
        }
        CP_COMMIT();
    }

    // layernorm(mask) -> sMh (fp16): warp per row, 2 rows/warp
    #pragma unroll
    for (int p = 0; p < 2; ++p) {
        const int r = warp + p * 8;
        const float4* mg = (const float4*)(mask + base + (size_t)r * 512);
        float4 vv[4];
        float s = 0.f, sq = 0.f;
        #pragma unroll
        for (int u = 0; u < 4; ++u) {
            vv[u] = mg[lane + 32 * u];
            s  += vv[u].x + vv[u].y + vv[u].z + vv[u].w;
            sq += vv[u].x * vv[u].x + vv[u].y * vv[u].y + vv[u].z * vv[u].z + vv[u].w * vv[u].w;
        }
        #pragma unroll
        for (int o = 16; o; o >>= 1) {
            s  += __shfl_xor_sync(0xffffffffu, s,  o);
            sq += __shfl_xor_sync(0xffffffffu, sq, o);
        }
        const float mu  = s * (1.f / 512.f);
        const float inv = rsqrtf(sq * (1.f / 512.f) - mu * mu + 1e-5f);
        const float4* gg = (const float4*)ln_g;
        const float4* bv = (const float4*)ln_b;
        uint2* mr = (uint2*)(sMh + r * PADH);
        #pragma unroll
        for (int u = 0; u < 4; ++u) {
            float4 g4 = gg[lane + 32 * u], b4 = bv[lane + 32 * u];
            float m0 = (vv[u].x - mu) * inv * g4.x + b4.x;
            float m1 = (vv[u].y - mu) * inv * g4.y + b4.y;
            float m2 = (vv[u].z - mu) * inv * g4.z + b4.z;
            float m3 = (vv[u].w - mu) * inv * g4.w + b4.w;
            mr[lane + 32 * u] = make_uint2(h2b(__floats2half2_rn(m0, m1)),
                                           h2b(__floats2half2_rn(m2, m3)));
        }
    }
    __syncthreads();

    // sym = (m m^T)/sqrt(C) via fp16 mma: warps 0,1
    if (warp < 2) {
        float acc4[4] = {0.f, 0.f, 0.f, 0.f};
        const int nb = warp * 8;
        #pragma unroll 4
        for (int k16 = 0; k16 < 32; ++k16) {
            const int kb = k16 * 16 + tig * 2;
            uint32_t aF[4], bF[2];
            aF[0] = *(const uint32_t*)(sMh + gid * PADH + kb);
            aF[1] = *(const uint32_t*)(sMh + (gid + 8) * PADH + kb);
            aF[2] = *(const uint32_t*)(sMh + gid * PADH + kb + 8);
            aF[3] = *(const uint32_t*)(sMh + (gid + 8) * PADH + kb + 8);
            bF[0] = *(const uint32_t*)(sMh + (nb + gid) * PADH + kb);
            bF[1] = *(const uint32_t*)(sMh + (nb + gid) * PADH + kb + 8);
            mma_f16(acc4, aF, bF);
        }
        const float S = 0.044194173824159216f;  // 1/sqrt(512)
        const int cc = nb + tig * 2;
        sSym[gid * 16 + cc]           = (gid == cc)         ? 0.f : acc4[0] * S;
        sSym[gid * 16 + cc + 1]       = (gid == cc + 1)     ? 0.f : acc4[1] * S;
        sSym[(gid + 8) * 16 + cc]     = (gid + 8 == cc)     ? 0.f : acc4[2] * S;
        sSym[(gid + 8) * 16 + cc + 1] = (gid + 8 == cc + 1) ? 0.f : acc4[3] * S;
    }
    asm volatile("cp.async.wait_group 0;" ::: "memory");
    __syncthreads();

    // sim[h] = q_h k_h^T /8 + sym*beta[h] via fp16 mma: warp h
    {
        const int hb = warp * 64;
        const float bh = beta[warp];
        float acc8[2][4];
        #pragma unroll
        for (int nt = 0; nt < 2; ++nt)
            #pragma unroll
            for (int r = 0; r < 4; ++r) acc8[nt][r] = 0.f;

        #pragma unroll
        for (int k16 = 0; k16 < 4; ++k16) {
            const int kb = hb + k16 * 16 + tig * 2;
            uint32_t aF[4], bF[2];
            aF[0] = *(const uint32_t*)(sQh + gid * PADH + kb);
            aF[1] = *(const uint32_t*)(sQh + (gid + 8) * PADH + kb);
            aF[2] = *(const uint32_t*)(sQh + gid * PADH + kb + 8);
            aF[3] = *(const uint32_t*)(sQh + (gid + 8) * PADH + kb + 8);
            #pragma unroll
            for (int nt = 0; nt < 2; ++nt) {
                bF[0] = *(const uint32_t*)(sKh + (nt * 8 + gid) * PADH + kb);
                bF[1] = *(const uint32_t*)(sKh + (nt * 8 + gid) * PADH + kb + 8);
                mma_f16(acc8[nt], aF, bF);
            }
        }
        float* simh = sSim + warp * 256;
        #pragma unroll
        for (int nt = 0; nt < 2; ++nt) {
            const int c0 = nt * 8 + tig * 2;
            simh[gid * 16 + c0]           = acc8[nt][0] * 0.125f + sSym[gid * 16 + c0] * bh;
            simh[gid * 16 + c0 + 1]       = acc8[nt][1] * 0.125f + sSym[gid * 16 + c0 + 1] * bh;
            simh[(gid + 8) * 16 + c0]     = acc8[nt][2] * 0.125f + sSym[(gid + 8) * 16 + c0] * bh;
            simh[(gid + 8) * 16 + c0 + 1] = acc8[nt][3] * 0.125f + sSym[(gid + 8) * 16 + c0 + 1] * bh;
        }
    }
    __syncthreads();

    // softmax over j: one thread per (h,i) row
    if (tid < 128) {
        float* row = sSim + tid * 16;
        float mx = row[0];
        #pragma unroll
        for (int j = 1; j < 16; ++j) mx = fmaxf(mx, row[j]);
        float s = 0.f;
        #pragma unroll
        for (int j = 0; j < 16; ++j) { float e = __expf(row[j] - mx); row[j] = e; s += e; }
        const float inv = 1.f / s;
        #pragma unroll
        for (int j = 0; j < 16; ++j) row[j] *= inv;
    }
    __syncthreads();

    // ctx = attn @ v : thread owns 2 adjacent cols
    {
        const __half2* vg2 = (const __half2*)(g_v + base);
        float2 vr[16];
        #pragma unroll
        for (int j = 0; j < 16; ++j) vr[j] = __half22float2(vg2[j * 256 + tid]);
        const float* ab = sSim + warp * 256;
        __half2* cg2 = (__half2*)(g_ctx + base);
        #pragma unroll
        for (int i = 0; i < 16; ++i) {
            const float* ar = ab + i * 16;
            float a0 = 0.f, a1 = 0.f;
            #pragma unroll
            for (int j = 0; j < 16; ++j) {
                const float a = ar[j];
                a0 += a * vr[j].x;
                a1 += a * vr[j].y;
            }
            cg2[i * 256 + tid] = __floats2half2_rn(a0, a1);
        }
    }
}

// ---------------------------------------------------------------------------
// Launch
// ---------------------------------------------------------------------------
extern "C" void kernel_launch(void* const* d_in, const int* in_sizes, int n_in,
                              void* d_out, int out_size) {
    const float* x    = (const float*)d_in[0];
    const float* mask = (const float*)d_in[1];
    const float* w_q  = (const float*)d_in[2];
    const float* w_k  = (const float*)d_in[3];
    const float* w_v  = (const float*)d_in[4];
    const float* w_o  = (const float*)d_in[5];
    const float* b_o  = (const float*)d_in[6];
    const float* beta = (const float*)d_in[7];
    const float* ln_g = (const float*)d_in[8];
    const float* ln_b = (const float*)d_in[9];
    float* out = (float*)d_out;

    __half *xh, *wq, *wk, *wv, *wo, *q, *k, *v, *ctx;
    cudaGetSymbolAddress((void**)&xh,  g_xh);
    cudaGetSymbolAddress((void**)&wq,  g_wq);
    cudaGetSymbolAddress((void**)&wk,  g_wk);
    cudaGetSymbolAddress((void**)&wv,  g_wv);
    cudaGetSymbolAddress((void**)&wo,  g_wo);
    cudaGetSymbolAddress((void**)&q,   g_q);
    cudaGetSymbolAddress((void**)&k,   g_k);
    cudaGetSymbolAddress((void**)&v,   g_v);
    cudaGetSymbolAddress((void**)&ctx, g_ctx);

    const int bt = in_sizes[0] / C_DIM;       // B*T = 131072
    const int bb = bt / 16;                   // B   = 8192

    const int gemm_smem = 61440;
    const int attn_smem = 59136;
    cudaFuncSetAttribute(gemm_qkv_kernel, cudaFuncAttributeMaxDynamicSharedMemorySize, gemm_smem);
    cudaFuncSetAttribute(gemm_out_kernel, cudaFuncAttributeMaxDynamicSharedMemorySize, gemm_smem);
    cudaFuncSetAttribute(attn_kernel,     cudaFuncAttributeMaxDynamicSharedMemorySize, attn_smem);

    // fp32 -> fp16 converts (x + 4 weight matrices)
    const int n4x = bt * 128;                 // x float4 count
    cvt_kernel<<<(n4x + 255) / 256, 256>>>((const float4*)x,   (uint2*)xh, n4x);
    cvt_kernel<<<256, 256>>>((const float4*)w_q, (uint2*)wq, 65536);
    cvt_kernel<<<256, 256>>>((const float4*)w_k, (uint2*)wk, 65536);
    cvt_kernel<<<256, 256>>>((const float4*)w_v, (uint2*)wv, 65536);
    cvt_kernel<<<256, 256>>>((const float4*)w_o, (uint2*)wo, 65536);

    dim3 grid_qkv(12, bt / 128);
    dim3 grid_out(4,  bt / 128);
    gemm_qkv_kernel<<<grid_qkv, 256, gemm_smem>>>(xh, q, k, v);
    attn_kernel<<<bb, 256, attn_smem>>>(mask, ln_g, ln_b, beta);
    gemm_out_kernel<<<grid_out, 256, gemm_smem>>>(ctx, out, b_o);
}